// round 11
// baseline (speedup 1.0000x reference)
#include <cuda_runtime.h>
#include <cuda_bf16.h>
#include <cstdint>

#define BTOT 16384
#define PFULL 4416          // 64 z + 256 feat + 4096 zz (full)
#define PW2   2624          // 64 z + 256 feat + 2304 zz (8-aligned tri groups)
#define NGRP  288
#define NCH   41            // PW2 / 64
#define SQRTK 11.313708498984761f

__device__ float g_WpartT[4][PFULL * 64];   // [split][p][n]
__device__ __align__(16) __nv_bfloat16 g_Wh[64 * PW2];
__device__ __align__(16) __nv_bfloat16 g_Wl[64 * PW2];
__device__ float g_csq[64];
__device__ float g_bsum[64];
__device__ uchar2 g_gij[NGRP];

// -------- prep stage 1: fold over K (split-k 4), transposed output ----------
__global__ void prep_fold1(const float* __restrict__ qzw,
                           const float* __restrict__ qfw,
                           const float* __restrict__ qg,
                           const float* __restrict__ cq) {
  __shared__ float cq_s[64 * 32];
  const int tid = threadIdx.x;
  const int kbase = blockIdx.y * 32;
  for (int i = tid; i < 512; i += 256) {
    int row = i >> 3, q = i & 7;
    *(float4*)(cq_s + row * 32 + q * 4) =
        *(const float4*)(cq + row * 128 + kbase + q * 4);
  }
  __syncthreads();

  const int p  = blockIdx.x * 32 + (tid & 7) * 4;
  const int ng = tid >> 3;            // 32 groups x 2 charts
  const float* src; int stride, off;
  if (p < 64)       { src = qzw; stride = 64;   off = p; }
  else if (p < 320) { src = qfw; stride = 256;  off = p - 64; }
  else              { src = qg;  stride = 4096; off = p - 320; }
  src += (size_t)kbase * stride;

  float acc[2][4] = {};
  for (int k0 = 0; k0 < 32; k0 += 8) {
    float4 wv[8];
#pragma unroll
    for (int kk = 0; kk < 8; ++kk)
      wv[kk] = *(const float4*)(src + (size_t)(k0 + kk) * stride + off);
#pragma unroll
    for (int kk = 0; kk < 8; ++kk) {
#pragma unroll
      for (int j = 0; j < 2; ++j) {
        float cv = cq_s[(ng * 2 + j) * 32 + k0 + kk];
        acc[j][0] = fmaf(cv, wv[kk].x, acc[j][0]);
        acc[j][1] = fmaf(cv, wv[kk].y, acc[j][1]);
        acc[j][2] = fmaf(cv, wv[kk].z, acc[j][2]);
        acc[j][3] = fmaf(cv, wv[kk].w, acc[j][3]);
      }
    }
  }
  float* dst = g_WpartT[blockIdx.y];
#pragma unroll
  for (int j = 0; j < 2; ++j)
#pragma unroll
    for (int pp = 0; pp < 4; ++pp)
      dst[(size_t)(p + pp) * 64 + (ng * 2 + j)] = acc[j][pp];
}

// ------- prep stage 2: sum partials, tri-fold, hi/lo split, tables ----------
__global__ void prep_fold2() {
  const int tid = threadIdx.x;
  const int pl = blockIdx.x * 64 + (tid & 63);
  const int ng = tid >> 6;                 // 4 groups x 16 charts
  int srcp = -1, srcq = -1;
  if (pl < 320) {
    srcp = pl;
  } else {
    int t = pl - 320;
    int g = t >> 3, w8 = t & 7;
    int i = 0, cum = 0;
    for (int ii = 0; ii < 64; ++ii) {
      int cnt = 8 - (ii >> 3);
      if (g < cum + cnt) { i = ii; break; }
      cum += cnt;
    }
    int b = (i >> 3) + (g - cum);
    int j = b * 8 + w8;
    if (ng == 0 && w8 == 0)
      g_gij[g] = make_uchar2((unsigned char)i, (unsigned char)(b * 8));
    if (j >= i) {
      srcp = 320 + i * 64 + j;
      srcq = (j > i) ? (320 + j * 64 + i) : -1;
    }
  }
#pragma unroll
  for (int nq = 0; nq < 4; ++nq) {
    float v[4] = {0.f, 0.f, 0.f, 0.f};
    if (srcp >= 0) {
#pragma unroll
      for (int s = 0; s < 4; ++s) {
        float4 u = *(const float4*)(g_WpartT[s] + (size_t)srcp * 64 + ng * 16 + nq * 4);
        v[0] += u.x; v[1] += u.y; v[2] += u.z; v[3] += u.w;
      }
      if (srcq >= 0) {
#pragma unroll
        for (int s = 0; s < 4; ++s) {
          float4 u = *(const float4*)(g_WpartT[s] + (size_t)srcq * 64 + ng * 16 + nq * 4);
          v[0] += u.x; v[1] += u.y; v[2] += u.z; v[3] += u.w;
        }
      }
    }
#pragma unroll
    for (int cmp = 0; cmp < 4; ++cmp) {
      int n = ng * 16 + nq * 4 + cmp;
      __nv_bfloat16 h = __float2bfloat16(v[cmp]);
      g_Wh[(size_t)n * PW2 + pl] = h;
      g_Wl[(size_t)n * PW2 + pl] = __float2bfloat16(v[cmp] - __bfloat162float(h));
    }
  }
}

__global__ void prep_small(const float* __restrict__ cq,
                           const float* __restrict__ qzb,
                           const float* __restrict__ qfb) {
  int n = threadIdx.x;
  if (n >= 64) return;
  const float* r = cq + n * 128;
  float cs = 0.f, bs = 0.f;
  for (int d = 0; d < 64; ++d) cs = fmaf(r[d], r[d], cs);
  for (int k = 0; k < 128; ++k) bs = fmaf(r[k], qzb[k] + qfb[k], bs);
  g_csq[n] = cs;
  g_bsum[n] = bs;
}

// --------------------------- main kernel ------------------------------------
// 64 rows/CTA, grid 256, 2 CTAs/SM, homogeneous warps, (2m,4n) warp grid.
#define O_GIJ  0             // uchar2[288] = 576
#define O_ZSQ  576           // float[64]
#define O_CSQ  832
#define O_BSM  1088
#define O_RMX  1344
#define O_RIV  1600
#define O_ZS   1920          // float [64][68] = 17408
#define O_CT   19328         // float [64][64] = 16384 (transposed centers)
#define O_XH   35712         // bf16 [2][64][72] = 18432  (Sc overlaps)
#define O_XL   54144         // bf16 [2][64][72] = 18432  (zcS overlaps)
#define O_WH   72576         // bf16 [2][64][72] = 18432
#define O_WL   91008         // bf16 [2][64][72] = 18432
#define SMEMB  109440

__device__ __forceinline__ void mma16816(float* c, const uint32_t* a,
                                         const uint32_t* b) {
  asm volatile(
      "mma.sync.aligned.m16n8k16.row.col.f32.bf16.bf16.f32 "
      "{%0,%1,%2,%3},{%4,%5,%6,%7},{%8,%9},{%0,%1,%2,%3};"
      : "+f"(c[0]), "+f"(c[1]), "+f"(c[2]), "+f"(c[3])
      : "r"(a[0]), "r"(a[1]), "r"(a[2]), "r"(a[3]), "r"(b[0]), "r"(b[1]));
}
__device__ __forceinline__ void ldsm4(uint32_t* r, uint32_t saddr) {
  asm volatile(
      "ldmatrix.sync.aligned.m8n8.x4.shared.b16 {%0,%1,%2,%3},[%4];"
      : "=r"(r[0]), "=r"(r[1]), "=r"(r[2]), "=r"(r[3]) : "r"(saddr));
}
#define CP_ASYNC16(dst, src) \
  asm volatile("cp.async.cg.shared.global [%0], [%1], 16;" :: "r"(dst), "l"(src))
#define CP_COMMIT() asm volatile("cp.async.commit_group;" ::: "memory")
#define CP_WAIT0()  asm volatile("cp.async.wait_group 0;" ::: "memory")

__device__ __forceinline__ void split_store(char* xh, char* xl, const float* v) {
  uint32_t ph[4], plo[4];
#pragma unroll
  for (int j = 0; j < 4; ++j) {
    __nv_bfloat162 h2 = __float22bfloat162_rn(make_float2(v[2 * j], v[2 * j + 1]));
    ph[j] = *(uint32_t*)&h2;
    __nv_bfloat162 l2 = __float22bfloat162_rn(
        make_float2(v[2 * j] - __low2float(h2), v[2 * j + 1] - __high2float(h2)));
    plo[j] = *(uint32_t*)&l2;
  }
  *(uint4*)xh = *(uint4*)ph;
  *(uint4*)xl = *(uint4*)plo;
}

__global__ void __launch_bounds__(256, 2)
atlas_main(const float* __restrict__ z, const float* __restrict__ feat,
           const float* __restrict__ cq, float* __restrict__ out,
           int out_size) {
  extern __shared__ char sm[];
  float* zs   = (float*)(sm + O_ZS);    // stride 68
  float* ct   = (float*)(sm + O_CT);    // [d][col], stride 64
  uchar2* gij = (uchar2*)(sm + O_GIJ);
  float* zsq  = (float*)(sm + O_ZSQ);
  float* csqs = (float*)(sm + O_CSQ);
  float* bsm  = (float*)(sm + O_BSM);
  float* rmx  = (float*)(sm + O_RMX);
  float* riv  = (float*)(sm + O_RIV);
  float* Sc   = (float*)(sm + O_XH);    // stride 68, post-loop overlap
  float* zcS  = (float*)(sm + O_XL);    // stride 64, post-loop overlap

  const int tid = threadIdx.x, lane = tid & 31, w = tid >> 5;
  const int gid = lane >> 2, tg = lane & 3;
  const int r0 = blockIdx.x * 64;
  const uint32_t smb = (uint32_t)__cvta_generic_to_shared(sm);

  for (int i = tid; i < 1024; i += 256) {          // z: 64 rows x 16 float4
    int row = i >> 4, q = i & 15;
    *(float4*)(zs + row * 68 + q * 4) =
        ((const float4*)(z + (size_t)(r0 + row) * 64))[q];
  }
  for (int i = tid; i < 4096; i += 256) {          // centers transposed [d][n]
    int d = i >> 6, n = i & 63;
    ct[d * 64 + n] = cq[n * 128 + d];
  }
  for (int i = tid; i < NGRP; i += 256) gij[i] = g_gij[i];
  if (tid < 64) { csqs[tid] = g_csq[tid]; bsm[tid] = g_bsum[tid]; }
  __syncthreads();

  const int xr = tid >> 2, qtr = tid & 3;          // X-gen / zc role
  const float* zrow = zs + xr * 68;

  if (tid < 64) {
    float s = 0.f;
    const float* zr = zs + tid * 68;
    for (int d = 0; d < 64; ++d) s = fmaf(zr[d], zr[d], s);
    zsq[tid] = s;
  }

  // prologue: chunk 0 (z region) X-gen + W chunk 0 via cp.async, into buf 0
  {
#pragma unroll
    for (int g = 0; g < 2; ++g) {
      const int j0 = qtr * 16 + g * 8;
      float v[8];
      float4 u0 = *(const float4*)(zrow + j0);
      float4 u1 = *(const float4*)(zrow + j0 + 4);
      v[0] = u0.x; v[1] = u0.y; v[2] = u0.z; v[3] = u0.w;
      v[4] = u1.x; v[5] = u1.y; v[6] = u1.z; v[7] = u1.w;
      split_store(sm + O_XH + xr * 144 + j0 * 2, sm + O_XL + xr * 144 + j0 * 2, v);
    }
#pragma unroll
    for (int t = 0; t < 4; ++t) {
      int seg = tid * 4 + t;           // 0..1023
      int isLo = seg >> 9, s = seg & 511;
      int n = s >> 3, k8 = s & 7;
      uint32_t dst = smb + (isLo ? O_WL : O_WH) + n * 144 + k8 * 16;
      const char* src = (const char*)(isLo ? g_Wl : g_Wh) +
                        ((size_t)n * PW2) * 2 + k8 * 16;
      CP_ASYNC16(dst, src);
    }
    CP_COMMIT();
    CP_WAIT0();
  }
  __syncthreads();

  const int wm = w >> 2, wn = w & 3;       // 2m x 4n warp grid
  const int m_base = wm * 32, n_base = wn * 16;
  float acc[2][2][4] = {};
  float zc[16];
#pragma unroll
  for (int q = 0; q < 16; ++q) zc[q] = 0.f;

  const uint32_t aoff = ((lane & 15) * 72 + (lane >> 4) * 8) * 2;
  const uint32_t boff =
      (((((lane >> 4) << 3)) + (lane & 7)) * 72 + ((lane >> 3) & 1) * 8) * 2;
  const uint32_t XHb = smb + O_XH + m_base * 144 + aoff;
  const uint32_t XLb = smb + O_XL + m_base * 144 + aoff;
  const uint32_t WHb = smb + O_WH + n_base * 144 + boff;
  const uint32_t WLb = smb + O_WL + n_base * 144 + boff;

  for (int c = 0; c < NCH; ++c) {
    const int cb = c & 1, nb = cb ^ 1, cc = c + 1;
    // kick cp.async W for chunk cc into buf nb (overlaps MMA below)
    if (cc < NCH) {
#pragma unroll
      for (int t = 0; t < 4; ++t) {
        int seg = tid * 4 + t;
        int isLo = seg >> 9, s = seg & 511;
        int n = s >> 3, k8 = s & 7;
        uint32_t dst = smb + (isLo ? O_WL : O_WH) + nb * 9216 + n * 144 + k8 * 16;
        const char* src = (const char*)(isLo ? g_Wl : g_Wh) +
                          ((size_t)n * PW2 + cc * 64) * 2 + k8 * 16;
        CP_ASYNC16(dst, src);
      }
      CP_COMMIT();
    }
    // ---- MMA on buf cb (3-pass split, 64-wide K) ----
    const uint32_t xh0 = XHb + cb * 9216, xl0 = XLb + cb * 9216;
    const uint32_t wh0 = WHb + cb * 9216, wl0 = WLb + cb * 9216;
#pragma unroll
    for (int kh = 0; kh < 4; ++kh) {
      const uint32_t kb = kh * 32;
      uint32_t bh[4], bl[4];
      ldsm4(bh, wh0 + kb);
      ldsm4(bl, wl0 + kb);
#pragma unroll
      for (int mt = 0; mt < 2; ++mt) {
        uint32_t ah[4], al[4];
        ldsm4(ah, xh0 + mt * 2304 + kb);
        ldsm4(al, xl0 + mt * 2304 + kb);
#pragma unroll
        for (int nt = 0; nt < 2; ++nt) {
          mma16816(acc[mt][nt], ah, bh + nt * 2);
          mma16816(acc[mt][nt], ah, bl + nt * 2);
          mma16816(acc[mt][nt], al, bh + nt * 2);
        }
      }
    }
    // ---- produce X chunk cc into buf nb ----
    if (cc < NCH) {
      char* xhd = sm + O_XH + nb * 9216 + xr * 144;
      char* xld = sm + O_XL + nb * 9216 + xr * 144;
#pragma unroll
      for (int g = 0; g < 2; ++g) {
        const int j0 = qtr * 16 + g * 8;
        float v[8];
        if (cc < 5) {
          const float* fp = feat + (size_t)(r0 + xr) * 256 + (cc * 64 - 64) + j0;
          float4 u0 = *(const float4*)fp;
          float4 u1 = *(const float4*)(fp + 4);
          v[0] = u0.x; v[1] = u0.y; v[2] = u0.z; v[3] = u0.w;
          v[4] = u1.x; v[5] = u1.y; v[6] = u1.z; v[7] = u1.w;
        } else {
          uchar2 ij = gij[(cc - 5) * 8 + qtr * 2 + g];
          float sc = zrow[ij.x];
          float4 u0 = *(const float4*)(zrow + ij.y);
          float4 u1 = *(const float4*)(zrow + ij.y + 4);
          v[0] = sc * u0.x; v[1] = sc * u0.y; v[2] = sc * u0.z; v[3] = sc * u0.w;
          v[4] = sc * u1.x; v[5] = sc * u1.y; v[6] = sc * u1.z; v[7] = sc * u1.w;
        }
        split_store(xhd + j0 * 2, xld + j0 * 2, v);
      }
    }
    // ---- overlapped fp32 z.c slice (2 dims per chunk, broadcast loads) ----
    if (c < 32) {
      const int d0 = 2 * c;
      const float a0 = zrow[d0], a1 = zrow[d0 + 1];
      const float* ct0 = ct + d0 * 64 + qtr * 16;
      const float* ct1 = ct0 + 64;
#pragma unroll
      for (int q4 = 0; q4 < 4; ++q4) {
        float4 u = *(const float4*)(ct0 + q4 * 4);
        float4 vv = *(const float4*)(ct1 + q4 * 4);
        zc[q4 * 4 + 0] = fmaf(a0, u.x, fmaf(a1, vv.x, zc[q4 * 4 + 0]));
        zc[q4 * 4 + 1] = fmaf(a0, u.y, fmaf(a1, vv.y, zc[q4 * 4 + 1]));
        zc[q4 * 4 + 2] = fmaf(a0, u.z, fmaf(a1, vv.z, zc[q4 * 4 + 2]));
        zc[q4 * 4 + 3] = fmaf(a0, u.w, fmaf(a1, vv.w, zc[q4 * 4 + 3]));
      }
    }
    if (cc < NCH) CP_WAIT0();
    __syncthreads();
  }

  // ---- dump gem + zc into smem (X buffers dead) ----
#pragma unroll
  for (int mt = 0; mt < 2; ++mt)
#pragma unroll
    for (int nt = 0; nt < 2; ++nt)
#pragma unroll
      for (int q = 0; q < 4; ++q) {
        const int row = m_base + mt * 16 + gid + (q >> 1) * 8;
        const int col = n_base + nt * 8 + tg * 2 + (q & 1);
        Sc[row * 68 + col] = acc[mt][nt][q];
      }
#pragma unroll
  for (int q = 0; q < 16; ++q) zcS[xr * 64 + qtr * 16 + q] = zc[q];
  __syncthreads();

  // ---- scoring: thread = (row, 16 cols) ----
  {
    const float zq = zsq[xr];
    const float tau = fmaxf(SQRTK * fmaxf(1.f - zq, 1e-3f) * 0.5f, 0.01f);
    const float invlam = (1.f - fminf(zq, 0.999f) + 1e-3f) * 0.5f;
    const float dn1 = 1.f - zq;
#pragma unroll 4
    for (int q = 0; q < 16; ++q) {
      const int col = qtr * 16 + q;
      const float gem = Sc[xr * 68 + col];
      const float cq2 = csqs[col];
      const float dsq = zq + cq2 - 2.f * zcS[xr * 64 + col];
      const float denom = dn1 * (1.f - cq2) + 1e-3f;
      float arg = fmaxf(1.f + 2.f * dsq / denom, 1.001f);
      float dist = logf(arg + sqrtf((arg + 1.f) * (arg - 1.f)));
      Sc[xr * 68 + col] =
          -dist / tau + (gem + bsm[col]) * invlam * (1.f / SQRTK);
    }
  }
  __syncthreads();

  // ---- softmax + argmax ----
  const bool has_k = (out_size >= BTOT * 64 + BTOT);
  if (tid < 64) {
    float m = -1e30f; int am = 0;
    const float* sr = Sc + tid * 68;
    for (int n = 0; n < 64; ++n) {
      float v = sr[n];
      if (v > m) { m = v; am = n; }
    }
    float s = 0.f;
    for (int n = 0; n < 64; ++n) s += __expf(sr[n] - m);
    rmx[tid] = m;
    riv[tid] = 1.f / s;
    if (has_k) out[BTOT * 64 + r0 + tid] = (float)am;
  }
  __syncthreads();
  for (int i = tid; i < 1024; i += 256) {           // 64 rows x 16 float4
    int r = i >> 4, q = i & 15;
    float mv = rmx[r], iv = riv[r];
    const float* sr = Sc + r * 68 + q * 4;
    float4 o;
    o.x = __expf(sr[0] - mv) * iv;
    o.y = __expf(sr[1] - mv) * iv;
    o.z = __expf(sr[2] - mv) * iv;
    o.w = __expf(sr[3] - mv) * iv;
    *(float4*)(out + (size_t)(r0 + r) * 64 + q * 4) = o;
  }
}

// ----------------------------------------------------------------------------
extern "C" void kernel_launch(void* const* d_in, const int* in_sizes, int n_in,
                              void* d_out, int out_size) {
  const float* z    = (const float*)d_in[0];
  const float* feat = (const float*)d_in[1];
  const float* qzw  = (const float*)d_in[2];
  const float* qzb  = (const float*)d_in[3];
  const float* qfw  = (const float*)d_in[4];
  const float* qfb  = (const float*)d_in[5];
  const float* qg   = (const float*)d_in[6];
  const float* cq   = (const float*)d_in[7];
  float* out = (float*)d_out;

  prep_fold1<<<dim3(PFULL / 32, 4), 256>>>(qzw, qfw, qg, cq);
  prep_fold2<<<NCH, 256>>>();
  prep_small<<<1, 64>>>(cq, qzb, qfb);
  cudaFuncSetAttribute(atlas_main, cudaFuncAttributeMaxDynamicSharedMemorySize,
                       SMEMB);
  atlas_main<<<BTOT / 64, 256, SMEMB>>>(z, feat, cq, out, out_size);
}

// round 12
// speedup vs baseline: 1.1805x; 1.1805x over previous
#include <cuda_runtime.h>
#include <cuda_bf16.h>
#include <cstdint>

#define BTOT 16384
#define PFULL 4416          // 64 z + 256 feat + 4096 zz (full)
#define PW2   2624          // 64 z + 256 feat + 2304 zz (8-aligned tri groups)
#define NGRP  288
#define NCH   41            // PW2 / 64
#define NSPL  8
#define SQRTK 11.313708498984761f

__device__ float g_WpartT[NSPL][PFULL * 64];   // [split][p][n]
__device__ __align__(16) __nv_bfloat16 g_Wh[64 * PW2];
__device__ __align__(16) __nv_bfloat16 g_Wl[64 * PW2];
__device__ float g_csq[64];
__device__ float g_bsum[64];
__device__ uchar2 g_gij[NGRP];

// -------- prep stage 1: fold over K (split-k 8), transposed output ----------
__global__ void prep_fold1(const float* __restrict__ qzw,
                           const float* __restrict__ qfw,
                           const float* __restrict__ qg,
                           const float* __restrict__ cq) {
  __shared__ float cq_s[64 * 16];
  const int tid = threadIdx.x;
  const int kbase = blockIdx.y * 16;
  for (int i = tid; i < 256; i += 256) {
    int row = i >> 2, q = i & 3;
    *(float4*)(cq_s + row * 16 + q * 4) =
        *(const float4*)(cq + row * 128 + kbase + q * 4);
  }
  __syncthreads();

  const int p  = blockIdx.x * 32 + (tid & 7) * 4;
  const int ng = tid >> 3;            // 32 groups x 2 charts
  const float* src; int stride, off;
  if (p < 64)       { src = qzw; stride = 64;   off = p; }
  else if (p < 320) { src = qfw; stride = 256;  off = p - 64; }
  else              { src = qg;  stride = 4096; off = p - 320; }
  src += (size_t)kbase * stride;

  float acc[2][4] = {};
  for (int k0 = 0; k0 < 16; k0 += 8) {
    float4 wv[8];
#pragma unroll
    for (int kk = 0; kk < 8; ++kk)
      wv[kk] = *(const float4*)(src + (size_t)(k0 + kk) * stride + off);
#pragma unroll
    for (int kk = 0; kk < 8; ++kk) {
#pragma unroll
      for (int j = 0; j < 2; ++j) {
        float cv = cq_s[(ng * 2 + j) * 16 + k0 + kk];
        acc[j][0] = fmaf(cv, wv[kk].x, acc[j][0]);
        acc[j][1] = fmaf(cv, wv[kk].y, acc[j][1]);
        acc[j][2] = fmaf(cv, wv[kk].z, acc[j][2]);
        acc[j][3] = fmaf(cv, wv[kk].w, acc[j][3]);
      }
    }
  }
  float* dst = g_WpartT[blockIdx.y];
#pragma unroll
  for (int j = 0; j < 2; ++j)
#pragma unroll
    for (int pp = 0; pp < 4; ++pp)
      dst[(size_t)(p + pp) * 64 + (ng * 2 + j)] = acc[j][pp];
}

// ------- prep stage 2: sum partials, tri-fold, hi/lo split, tables ----------
__global__ void prep_fold2() {
  const int tid = threadIdx.x;
  const int pl = blockIdx.x * 64 + (tid & 63);
  const int ng = tid >> 6;                 // 4 groups x 16 charts
  int srcp = -1, srcq = -1;
  if (pl < 320) {
    srcp = pl;
  } else {
    int t = pl - 320;
    int g = t >> 3, w8 = t & 7;
    int i = 0, cum = 0;
    for (int ii = 0; ii < 64; ++ii) {
      int cnt = 8 - (ii >> 3);
      if (g < cum + cnt) { i = ii; break; }
      cum += cnt;
    }
    int b = (i >> 3) + (g - cum);
    int j = b * 8 + w8;
    if (ng == 0 && w8 == 0)
      g_gij[g] = make_uchar2((unsigned char)i, (unsigned char)(b * 8));
    if (j >= i) {
      srcp = 320 + i * 64 + j;
      srcq = (j > i) ? (320 + j * 64 + i) : -1;
    }
  }
#pragma unroll
  for (int nq = 0; nq < 4; ++nq) {
    float v[4] = {0.f, 0.f, 0.f, 0.f};
    if (srcp >= 0) {
#pragma unroll
      for (int s = 0; s < NSPL; ++s) {
        float4 u = *(const float4*)(g_WpartT[s] + (size_t)srcp * 64 + ng * 16 + nq * 4);
        v[0] += u.x; v[1] += u.y; v[2] += u.z; v[3] += u.w;
      }
      if (srcq >= 0) {
#pragma unroll
        for (int s = 0; s < NSPL; ++s) {
          float4 u = *(const float4*)(g_WpartT[s] + (size_t)srcq * 64 + ng * 16 + nq * 4);
          v[0] += u.x; v[1] += u.y; v[2] += u.z; v[3] += u.w;
        }
      }
    }
#pragma unroll
    for (int cmp = 0; cmp < 4; ++cmp) {
      int n = ng * 16 + nq * 4 + cmp;
      __nv_bfloat16 h = __float2bfloat16(v[cmp]);
      g_Wh[(size_t)n * PW2 + pl] = h;
      g_Wl[(size_t)n * PW2 + pl] = __float2bfloat16(v[cmp] - __bfloat162float(h));
    }
  }
}

__global__ void prep_small(const float* __restrict__ cq,
                           const float* __restrict__ qzb,
                           const float* __restrict__ qfb) {
  int n = threadIdx.x;
  if (n >= 64) return;
  const float* r = cq + n * 128;
  float cs = 0.f, bs = 0.f;
  for (int d = 0; d < 64; ++d) cs = fmaf(r[d], r[d], cs);
  for (int k = 0; k < 128; ++k) bs = fmaf(r[k], qzb[k] + qfb[k], bs);
  g_csq[n] = cs;
  g_bsum[n] = bs;
}

// --------------------------- main kernel (R7-proven) -------------------------
// 64 rows per CTA, grid 256, 2 CTAs/SM.  smem layout (bytes):
#define O_ZS   0             // float [64][68] = 17408
#define O_CS   17408         // float [64][65] = 16640
#define O_GIJ  34048         // uchar2[288] = 576
#define O_ZSQ  34624
#define O_CSQ  34880
#define O_BSM  35136
#define O_RMX  35392
#define O_RIV  35648
#define O_XH   35904         // bf16 [2][64][72] = 18432  (Sc overlaps here)
#define O_XL   54336         // bf16 [2][64][72] = 18432
#define O_WH   72768         // bf16 [2][64][72] = 18432
#define O_WL   91200         // bf16 [2][64][72] = 18432
#define SMEMB  109632

__device__ __forceinline__ void mma16816(float* c, const uint32_t* a,
                                         const uint32_t* b) {
  asm volatile(
      "mma.sync.aligned.m16n8k16.row.col.f32.bf16.bf16.f32 "
      "{%0,%1,%2,%3},{%4,%5,%6,%7},{%8,%9},{%0,%1,%2,%3};"
      : "+f"(c[0]), "+f"(c[1]), "+f"(c[2]), "+f"(c[3])
      : "r"(a[0]), "r"(a[1]), "r"(a[2]), "r"(a[3]), "r"(b[0]), "r"(b[1]));
}

__device__ __forceinline__ void ldsm4(uint32_t* r, uint32_t saddr) {
  asm volatile(
      "ldmatrix.sync.aligned.m8n8.x4.shared.b16 {%0,%1,%2,%3},[%4];"
      : "=r"(r[0]), "=r"(r[1]), "=r"(r[2]), "=r"(r[3]) : "r"(saddr));
}

__device__ __forceinline__ void split_store(__nv_bfloat16* xh, __nv_bfloat16* xl,
                                            const float* v) {
  uint32_t ph[4], plo[4];
#pragma unroll
  for (int j = 0; j < 4; ++j) {
    __nv_bfloat162 h2 = __float22bfloat162_rn(make_float2(v[2 * j], v[2 * j + 1]));
    ph[j] = *(uint32_t*)&h2;
    __nv_bfloat162 l2 = __float22bfloat162_rn(
        make_float2(v[2 * j] - __low2float(h2), v[2 * j + 1] - __high2float(h2)));
    plo[j] = *(uint32_t*)&l2;
  }
  *(uint4*)xh = *(uint4*)ph;
  *(uint4*)xl = *(uint4*)plo;
}

__global__ void __launch_bounds__(256, 2)
atlas_main(const float* __restrict__ z, const float* __restrict__ feat,
           const float* __restrict__ cq, float* __restrict__ out,
           int out_size) {
  extern __shared__ char sm[];
  float* zs = (float*)(sm + O_ZS);                 // stride 68
  float* cs = (float*)(sm + O_CS);                 // stride 65
  uchar2* gij = (uchar2*)(sm + O_GIJ);
  float* zsq  = (float*)(sm + O_ZSQ);
  float* csqs = (float*)(sm + O_CSQ);
  float* bsm  = (float*)(sm + O_BSM);
  float* rmx  = (float*)(sm + O_RMX);
  float* riv  = (float*)(sm + O_RIV);
  float* Sc   = (float*)(sm + O_XH);               // overlap, used post-MMA
  __nv_bfloat16* Xh = (__nv_bfloat16*)(sm + O_XH); // per-buf 4608 elem
  __nv_bfloat16* Xl = (__nv_bfloat16*)(sm + O_XL);
  __nv_bfloat16* Wh = (__nv_bfloat16*)(sm + O_WH); // per-buf 4608 elem
  __nv_bfloat16* Wl = (__nv_bfloat16*)(sm + O_WL);

  const int tid = threadIdx.x, lane = tid & 31, w = tid >> 5;
  const int gid = lane >> 2, tg = lane & 3;
  const int r0 = blockIdx.x * 64;
  const uint32_t smb = (uint32_t)__cvta_generic_to_shared(sm);

  for (int i = tid; i < 1024; i += 256) {          // 64 rows x 16 float4
    int row = i >> 4, q = i & 15;
    *(float4*)(zs + row * 68 + q * 4) =
        ((const float4*)(z + (size_t)(r0 + row) * 64))[q];
  }
  for (int i = tid; i < 1024; i += 256) {          // centers 64x64
    int n = i >> 4, q = i & 15;
    float4 v = *(const float4*)(cq + (i >> 4) * 128 + (i & 15) * 4);
    cs[n * 65 + q * 4 + 0] = v.x;
    cs[n * 65 + q * 4 + 1] = v.y;
    cs[n * 65 + q * 4 + 2] = v.z;
    cs[n * 65 + q * 4 + 3] = v.w;
  }
  for (int i = tid; i < NGRP; i += 256) gij[i] = g_gij[i];
  if (tid < 64) { csqs[tid] = g_csq[tid]; bsm[tid] = g_bsum[tid]; }
  __syncthreads();
  if (tid < 64) {
    float s = 0.f;
    const float* zr = zs + tid * 68;
    for (int d = 0; d < 64; ++d) s = fmaf(zr[d], zr[d], s);
    zsq[tid] = s;
  }

  const int grow = tid >> 2, qtr = tid & 3;        // X-gen role
  const float* zrow = zs + grow * 68;
  const int wrow = tid >> 2, wcol = (tid & 3) * 16; // W-load role

  // prologue: chunk 0 (pure z region) + W0 into buf 0
  {
#pragma unroll
    for (int g = 0; g < 2; ++g) {
      int pb = qtr * 16 + g * 8;
      float v[8];
      float4 u0 = *(const float4*)(zrow + pb);
      float4 u1 = *(const float4*)(zrow + pb + 4);
      v[0] = u0.x; v[1] = u0.y; v[2] = u0.z; v[3] = u0.w;
      v[4] = u1.x; v[5] = u1.y; v[6] = u1.z; v[7] = u1.w;
      split_store(Xh + grow * 72 + pb, Xl + grow * 72 + pb, v);
    }
    const __nv_bfloat16* gh = g_Wh + (size_t)wrow * PW2 + wcol;
    const __nv_bfloat16* gl = g_Wl + (size_t)wrow * PW2 + wcol;
    *(uint4*)(Wh + wrow * 72 + wcol)     = *(const uint4*)gh;
    *(uint4*)(Wh + wrow * 72 + wcol + 8) = *(const uint4*)(gh + 8);
    *(uint4*)(Wl + wrow * 72 + wcol)     = *(const uint4*)gl;
    *(uint4*)(Wl + wrow * 72 + wcol + 8) = *(const uint4*)(gl + 8);
  }
  __syncthreads();

  const int wm = w >> 2, wn = w & 3;       // 2 x 4 warp grid
  const int m_base = wm * 32, n_base = wn * 16;
  float acc[2][2][4] = {};

  const uint32_t aoff = ((lane & 15) * 72 + (lane >> 4) * 8) * 2;
  const uint32_t boff =
      (((((lane >> 4) << 3)) + (lane & 7)) * 72 + ((lane >> 3) & 1) * 8) * 2;
  const uint32_t XHb = smb + O_XH + m_base * 144 + aoff;
  const uint32_t XLb = smb + O_XL + m_base * 144 + aoff;
  const uint32_t WHb = smb + O_WH + n_base * 144 + boff;
  const uint32_t WLb = smb + O_WL + n_base * 144 + boff;

  for (int c = 0; c < NCH; ++c) {
    const int cb = c & 1, nb = cb ^ 1, cc = c + 1;
    // stage next W chunk (LDG latency hidden under MMAs; L1-cached path)
    uint4 whr[2], wlr[2];
    if (cc < NCH) {
      const __nv_bfloat16* gh = g_Wh + (size_t)wrow * PW2 + cc * 64 + wcol;
      const __nv_bfloat16* gl = g_Wl + (size_t)wrow * PW2 + cc * 64 + wcol;
      whr[0] = *(const uint4*)gh; whr[1] = *(const uint4*)(gh + 8);
      wlr[0] = *(const uint4*)gl; wlr[1] = *(const uint4*)(gl + 8);
    }
    // MMA on buf cb (3-pass split, 64-wide K)
    const uint32_t xh0 = XHb + cb * 9216, xl0 = XLb + cb * 9216;
    const uint32_t wh0 = WHb + cb * 9216, wl0 = WLb + cb * 9216;
#pragma unroll
    for (int kh = 0; kh < 4; ++kh) {
      const uint32_t kb = kh * 32;
      uint32_t bh[4], bl[4];
      ldsm4(bh, wh0 + kb);
      ldsm4(bl, wl0 + kb);
#pragma unroll
      for (int mt = 0; mt < 2; ++mt) {
        uint32_t ah[4], al[4];
        ldsm4(ah, xh0 + mt * 2304 + kb);
        ldsm4(al, xl0 + mt * 2304 + kb);
#pragma unroll
        for (int nt = 0; nt < 2; ++nt) {
          mma16816(acc[mt][nt], ah, bh + nt * 2);
          mma16816(acc[mt][nt], ah, bl + nt * 2);
          mma16816(acc[mt][nt], al, bh + nt * 2);
        }
      }
    }
    // produce chunk cc into buf nb
    if (cc < NCH) {
      __nv_bfloat16* xhd = Xh + nb * 4608 + grow * 72 + qtr * 16;
      __nv_bfloat16* xld = Xl + nb * 4608 + grow * 72 + qtr * 16;
      const int pb = cc * 64 + qtr * 16;
#pragma unroll
      for (int g = 0; g < 2; ++g) {
        const int p = pb + g * 8;
        float v[8];
        float4 u0, u1;
        float scale = 1.f;
        if (p < 320) {                     // feat region (chunks 1..4)
          const float* fp = feat + (size_t)(r0 + grow) * 256 + (p - 64);
          u0 = *(const float4*)fp; u1 = *(const float4*)(fp + 4);
        } else {                           // zz aligned-group region
          uchar2 ij = gij[(p - 320) >> 3];
          scale = zrow[ij.x];
          u0 = *(const float4*)(zrow + ij.y);
          u1 = *(const float4*)(zrow + ij.y + 4);
        }
        v[0] = scale * u0.x; v[1] = scale * u0.y;
        v[2] = scale * u0.z; v[3] = scale * u0.w;
        v[4] = scale * u1.x; v[5] = scale * u1.y;
        v[6] = scale * u1.z; v[7] = scale * u1.w;
        split_store(xhd + g * 8, xld + g * 8, v);
      }
      *(uint4*)(Wh + nb * 4608 + wrow * 72 + wcol)     = whr[0];
      *(uint4*)(Wh + nb * 4608 + wrow * 72 + wcol + 8) = whr[1];
      *(uint4*)(Wl + nb * 4608 + wrow * 72 + wcol)     = wlr[0];
      *(uint4*)(Wl + nb * 4608 + wrow * 72 + wcol + 8) = wlr[1];
    }
    __syncthreads();
  }

  // ---- epilogue: fp32 z.c, hyperbolic score (Sc overlaps dead X buffer) ----
  const int colA = n_base + tg * 2;
#pragma unroll
  for (int mt = 0; mt < 2; ++mt) {
    const int row0 = m_base + mt * 16 + gid, row1 = row0 + 8;
    float zc[2][4] = {{0, 0, 0, 0}, {0, 0, 0, 0}};
    const float* z0 = zs + row0 * 68;
    const float* z1 = zs + row1 * 68;
    const float* c0 = cs + (colA)     * 65;
    const float* c1 = cs + (colA + 1) * 65;
    const float* c2 = cs + (colA + 8) * 65;
    const float* c3 = cs + (colA + 9) * 65;
    for (int d = 0; d < 64; ++d) {
      float a0 = z0[d], a1 = z1[d];
      float b0 = c0[d], b1 = c1[d], b2 = c2[d], b3 = c3[d];
      zc[0][0] = fmaf(a0, b0, zc[0][0]); zc[0][1] = fmaf(a0, b1, zc[0][1]);
      zc[0][2] = fmaf(a0, b2, zc[0][2]); zc[0][3] = fmaf(a0, b3, zc[0][3]);
      zc[1][0] = fmaf(a1, b0, zc[1][0]); zc[1][1] = fmaf(a1, b1, zc[1][1]);
      zc[1][2] = fmaf(a1, b2, zc[1][2]); zc[1][3] = fmaf(a1, b3, zc[1][3]);
    }
#pragma unroll
    for (int nt = 0; nt < 2; ++nt) {
#pragma unroll
      for (int q = 0; q < 4; ++q) {
        const int rh = q >> 1;
        const int row = rh ? row1 : row0;
        const int col = colA + nt * 8 + (q & 1);
        const float gem = acc[mt][nt][q];
        const float zq = zsq[row], cq2 = csqs[col];
        const float zcv = zc[rh][nt * 2 + (q & 1)];
        float dsq = zq + cq2 - 2.f * zcv;
        float denom = (1.f - zq) * (1.f - cq2) + 1e-3f;
        float arg = fmaxf(1.f + 2.f * dsq / denom, 1.001f);
        float dist = logf(arg + sqrtf((arg + 1.f) * (arg - 1.f)));
        float tau = fmaxf(SQRTK * fmaxf(1.f - zq, 1e-3f) * 0.5f, 0.01f);
        float r2 = fminf(zq, 0.999f);
        float invlam = (1.f - r2 + 1e-3f) * 0.5f;
        Sc[row * 68 + col] =
            -dist / tau + (gem + bsm[col]) * invlam * (1.f / SQRTK);
      }
    }
  }
  __syncthreads();

  // ---- softmax + argmax ----
  const bool has_k = (out_size >= BTOT * 64 + BTOT);
  if (tid < 64) {
    float m = -1e30f; int am = 0;
    const float* sr = Sc + tid * 68;
    for (int n = 0; n < 64; ++n) {
      float v = sr[n];
      if (v > m) { m = v; am = n; }
    }
    float s = 0.f;
    for (int n = 0; n < 64; ++n) s += __expf(sr[n] - m);
    rmx[tid] = m;
    riv[tid] = 1.f / s;
    if (has_k) out[BTOT * 64 + r0 + tid] = (float)am;
  }
  __syncthreads();
  for (int i = tid; i < 1024; i += 256) {           // 64 rows x 16 float4
    int r = i >> 4, q = i & 15;
    float mv = rmx[r], iv = riv[r];
    const float* sr = Sc + r * 68 + q * 4;
    float4 o;
    o.x = __expf(sr[0] - mv) * iv;
    o.y = __expf(sr[1] - mv) * iv;
    o.z = __expf(sr[2] - mv) * iv;
    o.w = __expf(sr[3] - mv) * iv;
    *(float4*)(out + (size_t)(r0 + r) * 64 + q * 4) = o;
  }
}

// ----------------------------------------------------------------------------
extern "C" void kernel_launch(void* const* d_in, const int* in_sizes, int n_in,
                              void* d_out, int out_size) {
  const float* z    = (const float*)d_in[0];
  const float* feat = (const float*)d_in[1];
  const float* qzw  = (const float*)d_in[2];
  const float* qzb  = (const float*)d_in[3];
  const float* qfw  = (const float*)d_in[4];
  const float* qfb  = (const float*)d_in[5];
  const float* qg   = (const float*)d_in[6];
  const float* cq   = (const float*)d_in[7];
  float* out = (float*)d_out;

  prep_fold1<<<dim3(PFULL / 32, NSPL), 256>>>(qzw, qfw, qg, cq);
  prep_fold2<<<NCH, 256>>>();
  prep_small<<<1, 64>>>(cq, qzb, qfb);
  cudaFuncSetAttribute(atlas_main, cudaFuncAttributeMaxDynamicSharedMemorySize,
                       SMEMB);
  atlas_main<<<BTOT / 64, 256, SMEMB>>>(z, feat, cq, out, out_size);
}

// round 14
// speedup vs baseline: 1.3411x; 1.1361x over previous
#include <cuda_runtime.h>
#include <cuda_bf16.h>
#include <cstdint>

#define BTOT 16384
#define PFULL 4416          // 64 z + 256 feat + 4096 zz (full)
#define PW2   2624          // 64 z + 256 feat + 2304 zz (8-aligned tri groups)
#define NGRP  288
#define NCH   41            // PW2 / 64
#define NSPL  8
#define SQRTK 11.313708498984761f

__device__ float g_WpartT[NSPL][PFULL * 64];   // [split][p][n]
// W in mma B-fragment order: [c][kh][wn][lane] -> uint4 (8 bf16)
__device__ __align__(16) __nv_bfloat16 g_WfH[NCH * 512 * 8];
__device__ __align__(16) __nv_bfloat16 g_WfL[NCH * 512 * 8];
__device__ float g_csq[64];
__device__ float g_bsum[64];
__device__ uchar2 g_gij[NGRP];

// -------- prep stage 1: fold over K (split-k 8), transposed output ----------
__global__ void prep_fold1(const float* __restrict__ qzw,
                           const float* __restrict__ qfw,
                           const float* __restrict__ qg,
                           const float* __restrict__ cq) {
  __shared__ float cq_s[64 * 16];
  const int tid = threadIdx.x;
  const int kbase = blockIdx.y * 16;
  for (int i = tid; i < 256; i += 256) {
    int row = i >> 2, q = i & 3;
    *(float4*)(cq_s + row * 16 + q * 4) =
        *(const float4*)(cq + row * 128 + kbase + q * 4);
  }
  __syncthreads();

  const int p  = blockIdx.x * 32 + (tid & 7) * 4;
  const int ng = tid >> 3;            // 32 groups x 2 charts
  const float* src; int stride, off;
  if (p < 64)       { src = qzw; stride = 64;   off = p; }
  else if (p < 320) { src = qfw; stride = 256;  off = p - 64; }
  else              { src = qg;  stride = 4096; off = p - 320; }
  src += (size_t)kbase * stride;

  float acc[2][4] = {};
  for (int k0 = 0; k0 < 16; k0 += 8) {
    float4 wv[8];
#pragma unroll
    for (int kk = 0; kk < 8; ++kk)
      wv[kk] = *(const float4*)(src + (size_t)(k0 + kk) * stride + off);
#pragma unroll
    for (int kk = 0; kk < 8; ++kk) {
#pragma unroll
      for (int j = 0; j < 2; ++j) {
        float cv = cq_s[(ng * 2 + j) * 16 + k0 + kk];
        acc[j][0] = fmaf(cv, wv[kk].x, acc[j][0]);
        acc[j][1] = fmaf(cv, wv[kk].y, acc[j][1]);
        acc[j][2] = fmaf(cv, wv[kk].z, acc[j][2]);
        acc[j][3] = fmaf(cv, wv[kk].w, acc[j][3]);
      }
    }
  }
  float* dst = g_WpartT[blockIdx.y];
#pragma unroll
  for (int j = 0; j < 2; ++j)
#pragma unroll
    for (int pp = 0; pp < 4; ++pp)
      dst[(size_t)(p + pp) * 64 + (ng * 2 + j)] = acc[j][pp];
}

// -- prep stage 2: sum partials, tri-fold, split, write FRAGMENT layout ------
__global__ void prep_fold2() {
  const int tid = threadIdx.x;
  const int pl = blockIdx.x * 64 + (tid & 63);
  const int ng = tid >> 6;                 // 4 groups x 16 charts
  int srcp = -1, srcq = -1;
  if (pl < 320) {
    srcp = pl;
  } else {
    int t = pl - 320;
    int g = t >> 3, w8 = t & 7;
    int i = 0, cum = 0;
    for (int ii = 0; ii < 64; ++ii) {
      int cnt = 8 - (ii >> 3);
      if (g < cum + cnt) { i = ii; break; }
      cum += cnt;
    }
    int b = (i >> 3) + (g - cum);
    int j = b * 8 + w8;
    if (ng == 0 && w8 == 0)
      g_gij[g] = make_uchar2((unsigned char)i, (unsigned char)(b * 8));
    if (j >= i) {
      srcp = 320 + i * 64 + j;
      srcq = (j > i) ? (320 + j * 64 + i) : -1;
    }
  }
  // fragment-address components from pl
  const int c = pl >> 6, kc = pl & 63, kh = kc >> 4, kr = kc & 15;
  const int tg = (kr >> 1) & 3, hik = (kr >> 3) & 1, pair = kr & 1;
#pragma unroll
  for (int nq = 0; nq < 4; ++nq) {
    float v[4] = {0.f, 0.f, 0.f, 0.f};
    if (srcp >= 0) {
#pragma unroll
      for (int s = 0; s < NSPL; ++s) {
        float4 u = *(const float4*)(g_WpartT[s] + (size_t)srcp * 64 + ng * 16 + nq * 4);
        v[0] += u.x; v[1] += u.y; v[2] += u.z; v[3] += u.w;
      }
      if (srcq >= 0) {
#pragma unroll
        for (int s = 0; s < NSPL; ++s) {
          float4 u = *(const float4*)(g_WpartT[s] + (size_t)srcq * 64 + ng * 16 + nq * 4);
          v[0] += u.x; v[1] += u.y; v[2] += u.z; v[3] += u.w;
        }
      }
    }
#pragma unroll
    for (int cmp = 0; cmp < 4; ++cmp) {
      int n = ng * 16 + nq * 4 + cmp;
      __nv_bfloat16 h = __float2bfloat16(v[cmp]);
      __nv_bfloat16 l = __float2bfloat16(v[cmp] - __bfloat162float(h));
      // block stride = 32 lanes * 8 bf16 = 256 (was the R13 bug: 128)
      size_t eidx = ((size_t)((c * 4 + kh) * 4 + (n >> 4)) * 256) +
                    ((n & 7) * 4 + tg) * 8 + ((n >> 3) & 1) * 4 + hik * 2 + pair;
      g_WfH[eidx] = h;
      g_WfL[eidx] = l;
    }
  }
}

__global__ void prep_small(const float* __restrict__ cq,
                           const float* __restrict__ qzb,
                           const float* __restrict__ qfb) {
  const int tid = threadIdx.x;         // 256 threads: 4 per chart
  const int n = tid >> 2, q = tid & 3;
  const float* r = cq + n * 128;
  float cs = 0.f, bs = 0.f;
  for (int d = q * 16; d < q * 16 + 16; ++d) cs = fmaf(r[d], r[d], cs);
  for (int k = q * 32; k < q * 32 + 32; ++k)
    bs = fmaf(r[k], qzb[k] + qfb[k], bs);
  cs += __shfl_xor_sync(0xffffffffu, cs, 1);
  cs += __shfl_xor_sync(0xffffffffu, cs, 2);
  bs += __shfl_xor_sync(0xffffffffu, bs, 1);
  bs += __shfl_xor_sync(0xffffffffu, bs, 2);
  if (q == 0) { g_csq[n] = cs; g_bsum[n] = bs; }
}

// --------------------------- main kernel ------------------------------------
// 64 rows per CTA, grid 256, 2 CTAs/SM; W streamed reg-direct from fragments.
#define O_ZS   0             // float [64][68] = 17408
#define O_CS   17408         // float [64][65] = 16640
#define O_GIJ  34048         // uchar2[288] = 576
#define O_ZSQ  34624
#define O_CSQ  34880
#define O_BSM  35136
#define O_RMX  35392
#define O_RIV  35648
#define O_XH   35904         // bf16 [2][64][72] = 18432  (Sc overlaps here)
#define O_XL   54336         // bf16 [2][64][72] = 18432
#define SMEMB  72768

__device__ __forceinline__ void mma16816(float* c, const uint32_t* a,
                                         const uint32_t* b) {
  asm volatile(
      "mma.sync.aligned.m16n8k16.row.col.f32.bf16.bf16.f32 "
      "{%0,%1,%2,%3},{%4,%5,%6,%7},{%8,%9},{%0,%1,%2,%3};"
      : "+f"(c[0]), "+f"(c[1]), "+f"(c[2]), "+f"(c[3])
      : "r"(a[0]), "r"(a[1]), "r"(a[2]), "r"(a[3]), "r"(b[0]), "r"(b[1]));
}

__device__ __forceinline__ void ldsm4(uint32_t* r, uint32_t saddr) {
  asm volatile(
      "ldmatrix.sync.aligned.m8n8.x4.shared.b16 {%0,%1,%2,%3},[%4];"
      : "=r"(r[0]), "=r"(r[1]), "=r"(r[2]), "=r"(r[3]) : "r"(saddr));
}

__device__ __forceinline__ void split_store(__nv_bfloat16* xh, __nv_bfloat16* xl,
                                            const float* v) {
  uint32_t ph[4], plo[4];
#pragma unroll
  for (int j = 0; j < 4; ++j) {
    __nv_bfloat162 h2 = __float22bfloat162_rn(make_float2(v[2 * j], v[2 * j + 1]));
    ph[j] = *(uint32_t*)&h2;
    __nv_bfloat162 l2 = __float22bfloat162_rn(
        make_float2(v[2 * j] - __low2float(h2), v[2 * j + 1] - __high2float(h2)));
    plo[j] = *(uint32_t*)&l2;
  }
  *(uint4*)xh = *(uint4*)ph;
  *(uint4*)xl = *(uint4*)plo;
}

__global__ void __launch_bounds__(256, 2)
atlas_main(const float* __restrict__ z, const float* __restrict__ feat,
           const float* __restrict__ cq, float* __restrict__ out,
           int out_size) {
  extern __shared__ char sm[];
  float* zs = (float*)(sm + O_ZS);                 // stride 68
  float* cs = (float*)(sm + O_CS);                 // stride 65
  uchar2* gij = (uchar2*)(sm + O_GIJ);
  float* zsq  = (float*)(sm + O_ZSQ);
  float* csqs = (float*)(sm + O_CSQ);
  float* bsm  = (float*)(sm + O_BSM);
  float* rmx  = (float*)(sm + O_RMX);
  float* riv  = (float*)(sm + O_RIV);
  float* Sc   = (float*)(sm + O_XH);               // overlap, used post-MMA
  __nv_bfloat16* Xh = (__nv_bfloat16*)(sm + O_XH); // per-buf 4608 elem
  __nv_bfloat16* Xl = (__nv_bfloat16*)(sm + O_XL);

  const int tid = threadIdx.x, lane = tid & 31, w = tid >> 5;
  const int gid = lane >> 2, tg = lane & 3;
  const int r0 = blockIdx.x * 64;
  const uint32_t smb = (uint32_t)__cvta_generic_to_shared(sm);

  for (int i = tid; i < 1024; i += 256) {          // 64 rows x 16 float4
    int row = i >> 4, q = i & 15;
    *(float4*)(zs + row * 68 + q * 4) =
        ((const float4*)(z + (size_t)(r0 + row) * 64))[q];
  }
  for (int i = tid; i < 1024; i += 256) {          // centers 64x64
    int n = i >> 4, q = i & 15;
    float4 v = *(const float4*)(cq + n * 128 + q * 4);
    cs[n * 65 + q * 4 + 0] = v.x;
    cs[n * 65 + q * 4 + 1] = v.y;
    cs[n * 65 + q * 4 + 2] = v.z;
    cs[n * 65 + q * 4 + 3] = v.w;
  }
  for (int i = tid; i < NGRP; i += 256) gij[i] = g_gij[i];
  if (tid < 64) { csqs[tid] = g_csq[tid]; bsm[tid] = g_bsum[tid]; }
  __syncthreads();
  if (tid < 64) {
    float s = 0.f;
    const float* zr = zs + tid * 68;
    for (int d = 0; d < 64; ++d) s = fmaf(zr[d], zr[d], s);
    zsq[tid] = s;
  }

  const int grow = tid >> 2, qtr = tid & 3;        // X-gen role
  const float* zrow = zs + grow * 68;

  const int wm = w >> 2, wn = w & 3;               // 2m x 4n warp grid
  const int m_base = wm * 32, n_base = wn * 16;
  float acc[2][2][4] = {};

  const uint4* WfH = (const uint4*)g_WfH;
  const uint4* WfL = (const uint4*)g_WfL;
  uint4 wh4[4], wl4[4];
  // preload W fragments for chunk 0
#pragma unroll
  for (int kh = 0; kh < 4; ++kh) {
    int idx = ((0 * 4 + kh) * 4 + wn) * 32 + lane;
    wh4[kh] = WfH[idx];
    wl4[kh] = WfL[idx];
  }

  // prologue: chunk 0 (pure z region) X into buf 0
  {
#pragma unroll
    for (int g = 0; g < 2; ++g) {
      int pb = qtr * 16 + g * 8;
      float v[8];
      float4 u0 = *(const float4*)(zrow + pb);
      float4 u1 = *(const float4*)(zrow + pb + 4);
      v[0] = u0.x; v[1] = u0.y; v[2] = u0.z; v[3] = u0.w;
      v[4] = u1.x; v[5] = u1.y; v[6] = u1.z; v[7] = u1.w;
      split_store(Xh + grow * 72 + pb, Xl + grow * 72 + pb, v);
    }
  }
  __syncthreads();

  const uint32_t aoff = ((lane & 15) * 72 + (lane >> 4) * 8) * 2;
  const uint32_t XHb = smb + O_XH + m_base * 144 + aoff;
  const uint32_t XLb = smb + O_XL + m_base * 144 + aoff;

  for (int c = 0; c < NCH; ++c) {
    const int cb = c & 1, nb = cb ^ 1, cc = c + 1;
    // ---- MMA on buf cb (3-pass split, 64-wide K); W from registers ----
    const uint32_t xh0 = XHb + cb * 9216, xl0 = XLb + cb * 9216;
#pragma unroll
    for (int kh = 0; kh < 4; ++kh) {
      const uint32_t kb = kh * 32;
      uint32_t bh[4], bl[4];
      bh[0] = wh4[kh].x; bh[1] = wh4[kh].y; bh[2] = wh4[kh].z; bh[3] = wh4[kh].w;
      bl[0] = wl4[kh].x; bl[1] = wl4[kh].y; bl[2] = wl4[kh].z; bl[3] = wl4[kh].w;
#pragma unroll
      for (int mt = 0; mt < 2; ++mt) {
        uint32_t ah[4], al[4];
        ldsm4(ah, xh0 + mt * 2304 + kb);
        ldsm4(al, xl0 + mt * 2304 + kb);
#pragma unroll
        for (int nt = 0; nt < 2; ++nt) {
          mma16816(acc[mt][nt], ah, bh + nt * 2);
          mma16816(acc[mt][nt], ah, bl + nt * 2);
          mma16816(acc[mt][nt], al, bh + nt * 2);
        }
      }
    }
    if (cc < NCH) {
      // fetch next W fragments (latency hidden by X-gen + barrier)
#pragma unroll
      for (int kh = 0; kh < 4; ++kh) {
        int idx = ((cc * 4 + kh) * 4 + wn) * 32 + lane;
        wh4[kh] = WfH[idx];
        wl4[kh] = WfL[idx];
      }
      // produce X chunk cc into buf nb
      __nv_bfloat16* xhd = Xh + nb * 4608 + grow * 72 + qtr * 16;
      __nv_bfloat16* xld = Xl + nb * 4608 + grow * 72 + qtr * 16;
      const int pb = cc * 64 + qtr * 16;
#pragma unroll
      for (int g = 0; g < 2; ++g) {
        const int p = pb + g * 8;
        float v[8];
        float4 u0, u1;
        float scale = 1.f;
        if (p < 320) {                     // feat region (chunks 1..4)
          const float* fp = feat + (size_t)(r0 + grow) * 256 + (p - 64);
          u0 = *(const float4*)fp; u1 = *(const float4*)(fp + 4);
        } else {                           // zz aligned-group region
          uchar2 ij = gij[(p - 320) >> 3];
          scale = zrow[ij.x];
          u0 = *(const float4*)(zrow + ij.y);
          u1 = *(const float4*)(zrow + ij.y + 4);
        }
        v[0] = scale * u0.x; v[1] = scale * u0.y;
        v[2] = scale * u0.z; v[3] = scale * u0.w;
        v[4] = scale * u1.x; v[5] = scale * u1.y;
        v[6] = scale * u1.z; v[7] = scale * u1.w;
        split_store(xhd + g * 8, xld + g * 8, v);
      }
    }
    __syncthreads();
  }

  // ---- epilogue: fp32 z.c, hyperbolic score (Sc overlaps dead X buffer) ----
  const int colA = n_base + tg * 2;
#pragma unroll
  for (int mt = 0; mt < 2; ++mt) {
    const int row0 = m_base + mt * 16 + gid, row1 = row0 + 8;
    float zc[2][4] = {{0, 0, 0, 0}, {0, 0, 0, 0}};
    const float* z0 = zs + row0 * 68;
    const float* z1 = zs + row1 * 68;
    const float* c0 = cs + (colA)     * 65;
    const float* c1 = cs + (colA + 1) * 65;
    const float* c2 = cs + (colA + 8) * 65;
    const float* c3 = cs + (colA + 9) * 65;
    for (int d = 0; d < 64; ++d) {
      float a0 = z0[d], a1 = z1[d];
      float b0 = c0[d], b1 = c1[d], b2 = c2[d], b3 = c3[d];
      zc[0][0] = fmaf(a0, b0, zc[0][0]); zc[0][1] = fmaf(a0, b1, zc[0][1]);
      zc[0][2] = fmaf(a0, b2, zc[0][2]); zc[0][3] = fmaf(a0, b3, zc[0][3]);
      zc[1][0] = fmaf(a1, b0, zc[1][0]); zc[1][1] = fmaf(a1, b1, zc[1][1]);
      zc[1][2] = fmaf(a1, b2, zc[1][2]); zc[1][3] = fmaf(a1, b3, zc[1][3]);
    }
#pragma unroll
    for (int nt = 0; nt < 2; ++nt) {
#pragma unroll
      for (int q = 0; q < 4; ++q) {
        const int rh = q >> 1;
        const int row = rh ? row1 : row0;
        const int col = colA + nt * 8 + (q & 1);
        const float gem = acc[mt][nt][q];
        const float zq = zsq[row], cq2 = csqs[col];
        const float zcv = zc[rh][nt * 2 + (q & 1)];
        float dsq = zq + cq2 - 2.f * zcv;
        float denom = (1.f - zq) * (1.f - cq2) + 1e-3f;
        float arg = fmaxf(1.f + 2.f * dsq / denom, 1.001f);
        float dist = logf(arg + sqrtf((arg + 1.f) * (arg - 1.f)));
        float tau = fmaxf(SQRTK * fmaxf(1.f - zq, 1e-3f) * 0.5f, 0.01f);
        float r2 = fminf(zq, 0.999f);
        float invlam = (1.f - r2 + 1e-3f) * 0.5f;
        Sc[row * 68 + col] =
            -dist / tau + (gem + bsm[col]) * invlam * (1.f / SQRTK);
      }
    }
  }
  __syncthreads();

  // ---- softmax + argmax ----
  const bool has_k = (out_size >= BTOT * 64 + BTOT);
  if (tid < 64) {
    float m = -1e30f; int am = 0;
    const float* sr = Sc + tid * 68;
    for (int n = 0; n < 64; ++n) {
      float v = sr[n];
      if (v > m) { m = v; am = n; }
    }
    float s = 0.f;
    for (int n = 0; n < 64; ++n) s += __expf(sr[n] - m);
    rmx[tid] = m;
    riv[tid] = 1.f / s;
    if (has_k) out[BTOT * 64 + r0 + tid] = (float)am;
  }
  __syncthreads();
  for (int i = tid; i < 1024; i += 256) {           // 64 rows x 16 float4
    int r = i >> 4, q = i & 15;
    float mv = rmx[r], iv = riv[r];
    const float* sr = Sc + r * 68 + q * 4;
    float4 o;
    o.x = __expf(sr[0] - mv) * iv;
    o.y = __expf(sr[1] - mv) * iv;
    o.z = __expf(sr[2] - mv) * iv;
    o.w = __expf(sr[3] - mv) * iv;
    *(float4*)(out + (size_t)(r0 + r) * 64 + q * 4) = o;
  }
}

// ----------------------------------------------------------------------------
extern "C" void kernel_launch(void* const* d_in, const int* in_sizes, int n_in,
                              void* d_out, int out_size) {
  const float* z    = (const float*)d_in[0];
  const float* feat = (const float*)d_in[1];
  const float* qzw  = (const float*)d_in[2];
  const float* qzb  = (const float*)d_in[3];
  const float* qfw  = (const float*)d_in[4];
  const float* qfb  = (const float*)d_in[5];
  const float* qg   = (const float*)d_in[6];
  const float* cq   = (const float*)d_in[7];
  float* out = (float*)d_out;

  prep_fold1<<<dim3(PFULL / 32, NSPL), 256>>>(qzw, qfw, qg, cq);
  prep_fold2<<<NCH, 256>>>();
  prep_small<<<1, 256>>>(cq, qzb, qfb);
  cudaFuncSetAttribute(atlas_main, cudaFuncAttributeMaxDynamicSharedMemorySize,
                       SMEMB);
  atlas_main<<<BTOT / 64, 256, SMEMB>>>(z, feat, cq, out, out_size);
}

// round 15
// speedup vs baseline: 1.3778x; 1.0273x over previous
#include <cuda_runtime.h>
#include <cuda_bf16.h>
#include <cstdint>

#define BTOT 16384
#define PFULL 4416          // 64 z + 256 feat + 4096 zz (full)
#define PW2   2624          // 64 z + 256 feat + 2304 zz (8-aligned tri groups)
#define NGRP  288
#define NCH   41            // PW2 / 64
#define NSPL  8
#define SQRTK 11.313708498984761f

__device__ float g_WpartT[NSPL][PFULL * 64];   // [split][p][n]
// W in mma B-fragment order: [c][kh][nb16][lane] -> uint4 (8 bf16)
__device__ __align__(16) __nv_bfloat16 g_WfH[NCH * 512 * 8];
__device__ __align__(16) __nv_bfloat16 g_WfL[NCH * 512 * 8];
__device__ float g_csq[64];
__device__ float g_bsum[64];
__device__ uchar2 g_gij[NGRP];

// -------- prep stage 1: fold over K (split-k 8), transposed output ----------
__global__ void prep_fold1(const float* __restrict__ qzw,
                           const float* __restrict__ qfw,
                           const float* __restrict__ qg,
                           const float* __restrict__ cq) {
  __shared__ float cq_s[64 * 16];
  const int tid = threadIdx.x;
  const int kbase = blockIdx.y * 16;
  for (int i = tid; i < 256; i += 256) {
    int row = i >> 2, q = i & 3;
    *(float4*)(cq_s + row * 16 + q * 4) =
        *(const float4*)(cq + row * 128 + kbase + q * 4);
  }
  __syncthreads();

  const int p  = blockIdx.x * 32 + (tid & 7) * 4;
  const int ng = tid >> 3;            // 32 groups x 2 charts
  const float* src; int stride, off;
  if (p < 64)       { src = qzw; stride = 64;   off = p; }
  else if (p < 320) { src = qfw; stride = 256;  off = p - 64; }
  else              { src = qg;  stride = 4096; off = p - 320; }
  src += (size_t)kbase * stride;

  float acc[2][4] = {};
  for (int k0 = 0; k0 < 16; k0 += 8) {
    float4 wv[8];
#pragma unroll
    for (int kk = 0; kk < 8; ++kk)
      wv[kk] = *(const float4*)(src + (size_t)(k0 + kk) * stride + off);
#pragma unroll
    for (int kk = 0; kk < 8; ++kk) {
#pragma unroll
      for (int j = 0; j < 2; ++j) {
        float cv = cq_s[(ng * 2 + j) * 16 + k0 + kk];
        acc[j][0] = fmaf(cv, wv[kk].x, acc[j][0]);
        acc[j][1] = fmaf(cv, wv[kk].y, acc[j][1]);
        acc[j][2] = fmaf(cv, wv[kk].z, acc[j][2]);
        acc[j][3] = fmaf(cv, wv[kk].w, acc[j][3]);
      }
    }
  }
  float* dst = g_WpartT[blockIdx.y];
#pragma unroll
  for (int j = 0; j < 2; ++j)
#pragma unroll
    for (int pp = 0; pp < 4; ++pp)
      dst[(size_t)(p + pp) * 64 + (ng * 2 + j)] = acc[j][pp];
}

// -- prep stage 2: sum partials, tri-fold, split, FRAGMENT layout (+small) ---
__global__ void prep_fold2(const float* __restrict__ cq,
                           const float* __restrict__ qzb,
                           const float* __restrict__ qfb) {
  const int tid = threadIdx.x;
  const int pl = blockIdx.x * 64 + (tid & 63);
  const int ngl = tid >> 6;                // 4 sub-groups x 4 charts
  const int n4 = blockIdx.y * 16 + ngl * 4;  // first of this thread's 4 charts
  int srcp = -1, srcq = -1;
  if (pl < 320) {
    srcp = pl;
  } else {
    int t = pl - 320;
    int g = t >> 3, w8 = t & 7;
    int i = 0, cum = 0;
    for (int ii = 0; ii < 64; ++ii) {
      int cnt = 8 - (ii >> 3);
      if (g < cum + cnt) { i = ii; break; }
      cum += cnt;
    }
    int b = (i >> 3) + (g - cum);
    int j = b * 8 + w8;
    if (blockIdx.y == 0 && ngl == 0 && w8 == 0)
      g_gij[g] = make_uchar2((unsigned char)i, (unsigned char)(b * 8));
    if (j >= i) {
      srcp = 320 + i * 64 + j;
      srcq = (j > i) ? (320 + j * 64 + i) : -1;
    }
  }
  // fragment-address components from pl
  const int c = pl >> 6, kc = pl & 63, kh = kc >> 4, kr = kc & 15;
  const int tg = (kr >> 1) & 3, hik = (kr >> 3) & 1, pair = kr & 1;

  float v[4] = {0.f, 0.f, 0.f, 0.f};
  if (srcp >= 0) {
#pragma unroll
    for (int s = 0; s < NSPL; ++s) {
      float4 u = *(const float4*)(g_WpartT[s] + (size_t)srcp * 64 + n4);
      v[0] += u.x; v[1] += u.y; v[2] += u.z; v[3] += u.w;
    }
    if (srcq >= 0) {
#pragma unroll
      for (int s = 0; s < NSPL; ++s) {
        float4 u = *(const float4*)(g_WpartT[s] + (size_t)srcq * 64 + n4);
        v[0] += u.x; v[1] += u.y; v[2] += u.z; v[3] += u.w;
      }
    }
  }
#pragma unroll
  for (int cmp = 0; cmp < 4; ++cmp) {
    int n = n4 + cmp;
    __nv_bfloat16 h = __float2bfloat16(v[cmp]);
    __nv_bfloat16 l = __float2bfloat16(v[cmp] - __bfloat162float(h));
    size_t eidx = ((size_t)((c * 4 + kh) * 4 + (n >> 4)) * 256) +
                  ((n & 7) * 4 + tg) * 8 + ((n >> 3) & 1) * 4 + hik * 2 + pair;
    g_WfH[eidx] = h;
    g_WfL[eidx] = l;
  }

  // merged prep_small (one block's worth of extra work)
  if (blockIdx.x == 0 && blockIdx.y == 0) {
    const int n = tid >> 2, q = tid & 3;
    const float* r = cq + n * 128;
    float cs = 0.f, bs = 0.f;
    for (int d = q * 16; d < q * 16 + 16; ++d) cs = fmaf(r[d], r[d], cs);
    for (int k = q * 32; k < q * 32 + 32; ++k)
      bs = fmaf(r[k], qzb[k] + qfb[k], bs);
    cs += __shfl_xor_sync(0xffffffffu, cs, 1);
    cs += __shfl_xor_sync(0xffffffffu, cs, 2);
    bs += __shfl_xor_sync(0xffffffffu, bs, 1);
    bs += __shfl_xor_sync(0xffffffffu, bs, 2);
    if (q == 0) { g_csq[n] = cs; g_bsum[n] = bs; }
  }
}

// --------------------------- main kernel ------------------------------------
// 64 rows/CTA, grid 256, 2 CTAs/SM; (4m,2n) warp grid; W reg-resident.
#define O_ZS   0             // float [64][68] = 17408
#define O_CS   17408         // float [64][65] = 16640
#define O_GIJ  34048         // uchar2[288] = 576
#define O_ZSQ  34624
#define O_CSQ  34880
#define O_BSM  35136
#define O_RMX  35392
#define O_RIV  35648
#define O_XH   35904         // bf16 [2][64][72] = 18432  (Sc overlaps here)
#define O_XL   54336         // bf16 [2][64][72] = 18432
#define SMEMB  72768

__device__ __forceinline__ void mma16816(float* c, const uint32_t* a,
                                         const uint32_t* b) {
  asm volatile(
      "mma.sync.aligned.m16n8k16.row.col.f32.bf16.bf16.f32 "
      "{%0,%1,%2,%3},{%4,%5,%6,%7},{%8,%9},{%0,%1,%2,%3};"
      : "+f"(c[0]), "+f"(c[1]), "+f"(c[2]), "+f"(c[3])
      : "r"(a[0]), "r"(a[1]), "r"(a[2]), "r"(a[3]), "r"(b[0]), "r"(b[1]));
}

__device__ __forceinline__ void ldsm4(uint32_t* r, uint32_t saddr) {
  asm volatile(
      "ldmatrix.sync.aligned.m8n8.x4.shared.b16 {%0,%1,%2,%3},[%4];"
      : "=r"(r[0]), "=r"(r[1]), "=r"(r[2]), "=r"(r[3]) : "r"(saddr));
}

__device__ __forceinline__ void split_store(__nv_bfloat16* xh, __nv_bfloat16* xl,
                                            const float* v) {
  uint32_t ph[4], plo[4];
#pragma unroll
  for (int j = 0; j < 4; ++j) {
    __nv_bfloat162 h2 = __float22bfloat162_rn(make_float2(v[2 * j], v[2 * j + 1]));
    ph[j] = *(uint32_t*)&h2;
    __nv_bfloat162 l2 = __float22bfloat162_rn(
        make_float2(v[2 * j] - __low2float(h2), v[2 * j + 1] - __high2float(h2)));
    plo[j] = *(uint32_t*)&l2;
  }
  *(uint4*)xh = *(uint4*)ph;
  *(uint4*)xl = *(uint4*)plo;
}

__global__ void __launch_bounds__(256, 2)
atlas_main(const float* __restrict__ z, const float* __restrict__ feat,
           const float* __restrict__ cq, float* __restrict__ out,
           int out_size) {
  extern __shared__ char sm[];
  float* zs = (float*)(sm + O_ZS);                 // stride 68
  float* cs = (float*)(sm + O_CS);                 // stride 65
  uchar2* gij = (uchar2*)(sm + O_GIJ);
  float* zsq  = (float*)(sm + O_ZSQ);
  float* csqs = (float*)(sm + O_CSQ);
  float* bsm  = (float*)(sm + O_BSM);
  float* rmx  = (float*)(sm + O_RMX);
  float* riv  = (float*)(sm + O_RIV);
  float* Sc   = (float*)(sm + O_XH);               // overlap, used post-MMA
  __nv_bfloat16* Xh = (__nv_bfloat16*)(sm + O_XH); // per-buf 4608 elem
  __nv_bfloat16* Xl = (__nv_bfloat16*)(sm + O_XL);

  const int tid = threadIdx.x, lane = tid & 31, w = tid >> 5;
  const int gid = lane >> 2, tg = lane & 3;
  const int r0 = blockIdx.x * 64;
  const uint32_t smb = (uint32_t)__cvta_generic_to_shared(sm);

  for (int i = tid; i < 1024; i += 256) {          // 64 rows x 16 float4
    int row = i >> 4, q = i & 15;
    *(float4*)(zs + row * 68 + q * 4) =
        ((const float4*)(z + (size_t)(r0 + row) * 64))[q];
  }
  for (int i = tid; i < 1024; i += 256) {          // centers 64x64
    int n = i >> 4, q = i & 15;
    float4 v = *(const float4*)(cq + n * 128 + q * 4);
    cs[n * 65 + q * 4 + 0] = v.x;
    cs[n * 65 + q * 4 + 1] = v.y;
    cs[n * 65 + q * 4 + 2] = v.z;
    cs[n * 65 + q * 4 + 3] = v.w;
  }
  for (int i = tid; i < NGRP; i += 256) gij[i] = g_gij[i];
  if (tid < 64) { csqs[tid] = g_csq[tid]; bsm[tid] = g_bsum[tid]; }
  __syncthreads();
  if (tid < 64) {
    float s = 0.f;
    const float* zr = zs + tid * 68;
    for (int d = 0; d < 64; ++d) s = fmaf(zr[d], zr[d], s);
    zsq[tid] = s;
  }

  const int grow = tid >> 2, qtr = tid & 3;        // X-gen role
  const float* zrow = zs + grow * 68;

  const int wm = w >> 1, wn = w & 1;               // 4m x 2n warp grid
  const int m_base = wm * 16, n_base = wn * 32;
  float acc[4][4] = {};

  const uint4* WfH = (const uint4*)g_WfH;
  const uint4* WfL = (const uint4*)g_WfL;
  uint4 wh4[4][2], wl4[4][2];                      // [kh][nb2]
  // preload W fragments for chunk 0
#pragma unroll
  for (int kh = 0; kh < 4; ++kh)
#pragma unroll
    for (int nb2 = 0; nb2 < 2; ++nb2) {
      int idx = ((0 * 4 + kh) * 4 + wn * 2 + nb2) * 32 + lane;
      wh4[kh][nb2] = WfH[idx];
      wl4[kh][nb2] = WfL[idx];
    }

  // prologue: chunk 0 (pure z region) X into buf 0
  {
#pragma unroll
    for (int g = 0; g < 2; ++g) {
      int pb = qtr * 16 + g * 8;
      float v[8];
      float4 u0 = *(const float4*)(zrow + pb);
      float4 u1 = *(const float4*)(zrow + pb + 4);
      v[0] = u0.x; v[1] = u0.y; v[2] = u0.z; v[3] = u0.w;
      v[4] = u1.x; v[5] = u1.y; v[6] = u1.z; v[7] = u1.w;
      split_store(Xh + grow * 72 + pb, Xl + grow * 72 + pb, v);
    }
  }
  __syncthreads();

  const uint32_t aoff = ((lane & 15) * 72 + (lane >> 4) * 8) * 2;
  const uint32_t XHb = smb + O_XH + m_base * 144 + aoff;
  const uint32_t XLb = smb + O_XL + m_base * 144 + aoff;

  for (int c = 0; c < NCH; ++c) {
    const int cb = c & 1, nb = cb ^ 1, cc = c + 1;
    // ---- MMA on buf cb (3-pass split); W from registers ----
    const uint32_t xh0 = XHb + cb * 9216, xl0 = XLb + cb * 9216;
#pragma unroll
    for (int kh = 0; kh < 4; ++kh) {
      const uint32_t kb = kh * 32;
      uint32_t ah[4], al[4];
      ldsm4(ah, xh0 + kb);
      ldsm4(al, xl0 + kb);
#pragma unroll
      for (int nb2 = 0; nb2 < 2; ++nb2) {
        const uint32_t* bh = (const uint32_t*)&wh4[kh][nb2];
        const uint32_t* bl = (const uint32_t*)&wl4[kh][nb2];
#pragma unroll
        for (int ntl = 0; ntl < 2; ++ntl) {
          const int nt = nb2 * 2 + ntl;
          mma16816(acc[nt], ah, bh + ntl * 2);
          mma16816(acc[nt], ah, bl + ntl * 2);
          mma16816(acc[nt], al, bh + ntl * 2);
        }
      }
    }
    if (cc < NCH) {
      // overwrite W regs with next chunk (MMA above already consumed them)
#pragma unroll
      for (int kh = 0; kh < 4; ++kh)
#pragma unroll
        for (int nb2 = 0; nb2 < 2; ++nb2) {
          int idx = ((cc * 4 + kh) * 4 + wn * 2 + nb2) * 32 + lane;
          wh4[kh][nb2] = WfH[idx];
          wl4[kh][nb2] = WfL[idx];
        }
      // produce X chunk cc into buf nb
      __nv_bfloat16* xhd = Xh + nb * 4608 + grow * 72 + qtr * 16;
      __nv_bfloat16* xld = Xl + nb * 4608 + grow * 72 + qtr * 16;
      const int pb = cc * 64 + qtr * 16;
#pragma unroll
      for (int g = 0; g < 2; ++g) {
        const int p = pb + g * 8;
        float v[8];
        float4 u0, u1;
        float scale = 1.f;
        if (p < 320) {                     // feat region (chunks 1..4)
          const float* fp = feat + (size_t)(r0 + grow) * 256 + (p - 64);
          u0 = *(const float4*)fp; u1 = *(const float4*)(fp + 4);
        } else {                           // zz aligned-group region
          uchar2 ij = gij[(p - 320) >> 3];
          scale = zrow[ij.x];
          u0 = *(const float4*)(zrow + ij.y);
          u1 = *(const float4*)(zrow + ij.y + 4);
        }
        v[0] = scale * u0.x; v[1] = scale * u0.y;
        v[2] = scale * u0.z; v[3] = scale * u0.w;
        v[4] = scale * u1.x; v[5] = scale * u1.y;
        v[6] = scale * u1.z; v[7] = scale * u1.w;
        split_store(xhd + g * 8, xld + g * 8, v);
      }
    }
    __syncthreads();
  }

  // ---- epilogue: fp32 z.c, hyperbolic score (Sc overlaps dead X buffer) ----
  const int colA = n_base + tg * 2;
  const int row0 = m_base + gid, row1 = row0 + 8;
  {
    float zcq[2][8];
#pragma unroll
    for (int r = 0; r < 2; ++r)
#pragma unroll
      for (int q = 0; q < 8; ++q) zcq[r][q] = 0.f;
    const float* z0 = zs + row0 * 68;
    const float* z1 = zs + row1 * 68;
    const float* cp[8];
#pragma unroll
    for (int nt = 0; nt < 4; ++nt) {
      cp[nt * 2]     = cs + (colA + nt * 8) * 65;
      cp[nt * 2 + 1] = cs + (colA + nt * 8 + 1) * 65;
    }
    for (int d = 0; d < 64; ++d) {
      float a0 = z0[d], a1 = z1[d];
#pragma unroll
      for (int q = 0; q < 8; ++q) {
        float b = cp[q][d];
        zcq[0][q] = fmaf(a0, b, zcq[0][q]);
        zcq[1][q] = fmaf(a1, b, zcq[1][q]);
      }
    }
#pragma unroll
    for (int nt = 0; nt < 4; ++nt) {
#pragma unroll
      for (int q = 0; q < 4; ++q) {
        const int rh = q >> 1;
        const int row = rh ? row1 : row0;
        const int col = colA + nt * 8 + (q & 1);
        const float gem = acc[nt][q];
        const float zq = zsq[row], cq2 = csqs[col];
        const float zcv = zcq[rh][nt * 2 + (q & 1)];
        float dsq = zq + cq2 - 2.f * zcv;
        float denom = (1.f - zq) * (1.f - cq2) + 1e-3f;
        float arg = fmaxf(1.f + 2.f * dsq / denom, 1.001f);
        float dist = logf(arg + sqrtf((arg + 1.f) * (arg - 1.f)));
        float tau = fmaxf(SQRTK * fmaxf(1.f - zq, 1e-3f) * 0.5f, 0.01f);
        float r2 = fminf(zq, 0.999f);
        float invlam = (1.f - r2 + 1e-3f) * 0.5f;
        Sc[row * 68 + col] =
            -dist / tau + (gem + bsm[col]) * invlam * (1.f / SQRTK);
      }
    }
  }
  __syncthreads();

  // ---- softmax + argmax ----
  const bool has_k = (out_size >= BTOT * 64 + BTOT);
  if (tid < 64) {
    float m = -1e30f; int am = 0;
    const float* sr = Sc + tid * 68;
    for (int n = 0; n < 64; ++n) {
      float v = sr[n];
      if (v > m) { m = v; am = n; }
    }
    float s = 0.f;
    for (int n = 0; n < 64; ++n) s += __expf(sr[n] - m);
    rmx[tid] = m;
    riv[tid] = 1.f / s;
    if (has_k) out[BTOT * 64 + r0 + tid] = (float)am;
  }
  __syncthreads();
  for (int i = tid; i < 1024; i += 256) {           // 64 rows x 16 float4
    int r = i >> 4, q = i & 15;
    float mv = rmx[r], iv = riv[r];
    const float* sr = Sc + r * 68 + q * 4;
    float4 o;
    o.x = __expf(sr[0] - mv) * iv;
    o.y = __expf(sr[1] - mv) * iv;
    o.z = __expf(sr[2] - mv) * iv;
    o.w = __expf(sr[3] - mv) * iv;
    *(float4*)(out + (size_t)(r0 + r) * 64 + q * 4) = o;
  }
}

// ----------------------------------------------------------------------------
extern "C" void kernel_launch(void* const* d_in, const int* in_sizes, int n_in,
                              void* d_out, int out_size) {
  const float* z    = (const float*)d_in[0];
  const float* feat = (const float*)d_in[1];
  const float* qzw  = (const float*)d_in[2];
  const float* qzb  = (const float*)d_in[3];
  const float* qfw  = (const float*)d_in[4];
  const float* qfb  = (const float*)d_in[5];
  const float* qg   = (const float*)d_in[6];
  const float* cq   = (const float*)d_in[7];
  float* out = (float*)d_out;

  prep_fold1<<<dim3(PFULL / 32, NSPL), 256>>>(qzw, qfw, qg, cq);
  prep_fold2<<<dim3(NCH, 4), 256>>>(cq, qzb, qfb);
  cudaFuncSetAttribute(atlas_main, cudaFuncAttributeMaxDynamicSharedMemorySize,
                       SMEMB);
  atlas_main<<<BTOT / 64, 256, SMEMB>>>(z, feat, cq, out, out_size);
}

// round 16
// speedup vs baseline: 1.3978x; 1.0145x over previous
#include <cuda_runtime.h>
#include <cuda_bf16.h>
#include <cstdint>

#define BTOT 16384
#define PFULL 4416          // 64 z + 256 feat + 4096 zz (full)
#define PW2   2624          // 64 z + 256 feat + 2304 zz (8-aligned tri groups)
#define NGRP  288
#define NCH   41            // PW2 / 64
#define NSPL  8
#define SQRTK 11.313708498984761f

__device__ float g_WpartT[NSPL][64 * PFULL];   // [split][n][p]
__device__ float g_Wsum[64 * PFULL];           // [n][p]
// W in mma B-fragment order: [c][kh][nb16][lane] -> uint4 (8 bf16)
__device__ __align__(16) __nv_bfloat16 g_WfH[NCH * 512 * 8];
__device__ __align__(16) __nv_bfloat16 g_WfL[NCH * 512 * 8];
__device__ float g_csq[64];
__device__ float g_bsum[64];
__device__ uchar2 g_gij[NGRP];

// ---- prep stage 1: fold over K (split-k 8), [n][p] coalesced output --------
__global__ void prep_fold1(const float* __restrict__ qzw,
                           const float* __restrict__ qfw,
                           const float* __restrict__ qg,
                           const float* __restrict__ cq) {
  __shared__ float cq_s[64 * 16];
  const int tid = threadIdx.x;
  const int kbase = blockIdx.y * 16;
  for (int i = tid; i < 256; i += 256) {
    int row = i >> 2, q = i & 3;
    *(float4*)(cq_s + row * 16 + q * 4) =
        *(const float4*)(cq + row * 128 + kbase + q * 4);
  }
  __syncthreads();

  const int p  = blockIdx.x * 32 + (tid & 7) * 4;
  const int ng = tid >> 3;            // 32 groups x 2 charts
  const float* src; int stride, off;
  if (p < 64)       { src = qzw; stride = 64;   off = p; }
  else if (p < 320) { src = qfw; stride = 256;  off = p - 64; }
  else              { src = qg;  stride = 4096; off = p - 320; }
  src += (size_t)kbase * stride;

  float acc[2][4] = {};
  for (int k0 = 0; k0 < 16; k0 += 8) {
    float4 wv[8];
#pragma unroll
    for (int kk = 0; kk < 8; ++kk)
      wv[kk] = *(const float4*)(src + (size_t)(k0 + kk) * stride + off);
#pragma unroll
    for (int kk = 0; kk < 8; ++kk) {
#pragma unroll
      for (int j = 0; j < 2; ++j) {
        float cv = cq_s[(ng * 2 + j) * 16 + k0 + kk];
        acc[j][0] = fmaf(cv, wv[kk].x, acc[j][0]);
        acc[j][1] = fmaf(cv, wv[kk].y, acc[j][1]);
        acc[j][2] = fmaf(cv, wv[kk].z, acc[j][2]);
        acc[j][3] = fmaf(cv, wv[kk].w, acc[j][3]);
      }
    }
  }
  float* dst = g_WpartT[blockIdx.y];
#pragma unroll
  for (int j = 0; j < 2; ++j)
    *(float4*)(dst + (size_t)(ng * 2 + j) * PFULL + p) = *(float4*)acc[j];
}

// ---- prep stage 1b: sum the 8 split partials (fully coalesced) -------------
__global__ void prep_sum() {
  size_t idx = (size_t)blockIdx.x * 256 + threadIdx.x;   // float4 index
  float4 s = make_float4(0.f, 0.f, 0.f, 0.f);
#pragma unroll
  for (int sp = 0; sp < NSPL; ++sp) {
    float4 u = ((const float4*)g_WpartT[sp])[idx];
    s.x += u.x; s.y += u.y; s.z += u.z; s.w += u.w;
  }
  ((float4*)g_Wsum)[idx] = s;
}

// ---- prep stage 2: tri-fold, hi/lo split, FRAGMENT layout (+small) ---------
__global__ void prep_fold2(const float* __restrict__ cq,
                           const float* __restrict__ qzb,
                           const float* __restrict__ qfb) {
  const int tid = threadIdx.x;
  const int pl = blockIdx.x * 64 + (tid & 15) * 4;   // quad of p
  const int n  = blockIdx.y * 16 + (tid >> 4);
  const float* wn = g_Wsum + (size_t)n * PFULL;

  float w4[4];
  if (pl < 320) {
    float4 u = *(const float4*)(wn + pl);
    w4[0] = u.x; w4[1] = u.y; w4[2] = u.z; w4[3] = u.w;
  } else {
    int t = pl - 320;
    int g = t >> 3;
    int i = 0, cum = 0;
    for (int ii = 0; ii < 64; ++ii) {
      int cnt = 8 - (ii >> 3);
      if (g < cum + cnt) { i = ii; break; }
      cum += cnt;
    }
    int b = (i >> 3) + (g - cum);
    int j0 = b * 8 + (t & 7);
    if (blockIdx.y == 0 && (tid >> 4) == 0 && (t & 7) == 0)
      g_gij[g] = make_uchar2((unsigned char)i, (unsigned char)(b * 8));
    float4 u = *(const float4*)(wn + 320 + i * 64 + j0);
    float tmp[4] = {u.x, u.y, u.z, u.w};
#pragma unroll
    for (int q = 0; q < 4; ++q) {
      int jq = j0 + q;
      if (jq > i)       w4[q] = tmp[q] + wn[320 + jq * 64 + i];
      else if (jq == i) w4[q] = tmp[q];
      else              w4[q] = 0.f;
    }
  }
#pragma unroll
  for (int q = 0; q < 4; ++q) {
    int plq = pl + q;
    int c = plq >> 6, kc = plq & 63, kh = kc >> 4, kr = kc & 15;
    int tg = (kr >> 1) & 3, hik = (kr >> 3) & 1, pair = kr & 1;
    __nv_bfloat16 h = __float2bfloat16(w4[q]);
    __nv_bfloat16 l = __float2bfloat16(w4[q] - __bfloat162float(h));
    size_t eidx = ((size_t)((c * 4 + kh) * 4 + (n >> 4)) * 256) +
                  ((n & 7) * 4 + tg) * 8 + ((n >> 3) & 1) * 4 + hik * 2 + pair;
    g_WfH[eidx] = h;
    g_WfL[eidx] = l;
  }

  // merged prep_small
  if (blockIdx.x == 0 && blockIdx.y == 0) {
    const int nn = tid >> 2, q = tid & 3;
    const float* r = cq + nn * 128;
    float cs = 0.f, bs = 0.f;
    for (int d = q * 16; d < q * 16 + 16; ++d) cs = fmaf(r[d], r[d], cs);
    for (int k = q * 32; k < q * 32 + 32; ++k)
      bs = fmaf(r[k], qzb[k] + qfb[k], bs);
    cs += __shfl_xor_sync(0xffffffffu, cs, 1);
    cs += __shfl_xor_sync(0xffffffffu, cs, 2);
    bs += __shfl_xor_sync(0xffffffffu, bs, 1);
    bs += __shfl_xor_sync(0xffffffffu, bs, 2);
    if (q == 0) { g_csq[nn] = cs; g_bsum[nn] = bs; }
  }
}

// --------------------------- main kernel ------------------------------------
// 64 rows/CTA, grid 256, 2 CTAs/SM; (4m,2n) warps; W reg-resident;
// 4-buffer X with one barrier per 2 chunks.
#define O_ZS   0             // float [64][68] = 17408
#define O_CS   17408         // float [64][65] = 16640
#define O_GIJ  34048         // uchar2[288] = 576
#define O_ZSQ  34624
#define O_CSQ  34880
#define O_BSM  35136
#define O_RMX  35392
#define O_RIV  35648
#define O_XH   35904         // bf16 [4][64][72] = 36864  (Sc overlaps here)
#define O_XL   72768         // bf16 [4][64][72] = 36864
#define SMEMB  109632

__device__ __forceinline__ void mma16816(float* c, const uint32_t* a,
                                         const uint32_t* b) {
  asm volatile(
      "mma.sync.aligned.m16n8k16.row.col.f32.bf16.bf16.f32 "
      "{%0,%1,%2,%3},{%4,%5,%6,%7},{%8,%9},{%0,%1,%2,%3};"
      : "+f"(c[0]), "+f"(c[1]), "+f"(c[2]), "+f"(c[3])
      : "r"(a[0]), "r"(a[1]), "r"(a[2]), "r"(a[3]), "r"(b[0]), "r"(b[1]));
}

__device__ __forceinline__ void ldsm4(uint32_t* r, uint32_t saddr) {
  asm volatile(
      "ldmatrix.sync.aligned.m8n8.x4.shared.b16 {%0,%1,%2,%3},[%4];"
      : "=r"(r[0]), "=r"(r[1]), "=r"(r[2]), "=r"(r[3]) : "r"(saddr));
}

__device__ __forceinline__ void split_store(__nv_bfloat16* xh, __nv_bfloat16* xl,
                                            const float* v) {
  uint32_t ph[4], plo[4];
#pragma unroll
  for (int j = 0; j < 4; ++j) {
    __nv_bfloat162 h2 = __float22bfloat162_rn(make_float2(v[2 * j], v[2 * j + 1]));
    ph[j] = *(uint32_t*)&h2;
    __nv_bfloat162 l2 = __float22bfloat162_rn(
        make_float2(v[2 * j] - __low2float(h2), v[2 * j + 1] - __high2float(h2)));
    plo[j] = *(uint32_t*)&l2;
  }
  *(uint4*)xh = *(uint4*)ph;
  *(uint4*)xl = *(uint4*)plo;
}

__global__ void __launch_bounds__(256, 2)
atlas_main(const float* __restrict__ z, const float* __restrict__ feat,
           const float* __restrict__ cq, float* __restrict__ out,
           int out_size) {
  extern __shared__ char sm[];
  float* zs = (float*)(sm + O_ZS);                 // stride 68
  float* cs = (float*)(sm + O_CS);                 // stride 65
  uchar2* gij = (uchar2*)(sm + O_GIJ);
  float* zsq  = (float*)(sm + O_ZSQ);
  float* csqs = (float*)(sm + O_CSQ);
  float* bsm  = (float*)(sm + O_BSM);
  float* rmx  = (float*)(sm + O_RMX);
  float* riv  = (float*)(sm + O_RIV);
  float* Sc   = (float*)(sm + O_XH);               // overlap, used post-MMA
  __nv_bfloat16* Xh = (__nv_bfloat16*)(sm + O_XH); // per-buf 4608 elem
  __nv_bfloat16* Xl = (__nv_bfloat16*)(sm + O_XL);

  const int tid = threadIdx.x, lane = tid & 31, w = tid >> 5;
  const int gid = lane >> 2, tg = lane & 3;
  const int r0 = blockIdx.x * 64;
  const uint32_t smb = (uint32_t)__cvta_generic_to_shared(sm);

  for (int i = tid; i < 1024; i += 256) {          // 64 rows x 16 float4
    int row = i >> 4, q = i & 15;
    *(float4*)(zs + row * 68 + q * 4) =
        ((const float4*)(z + (size_t)(r0 + row) * 64))[q];
  }
  for (int i = tid; i < 1024; i += 256) {          // centers 64x64
    int n = i >> 4, q = i & 15;
    float4 v = *(const float4*)(cq + n * 128 + q * 4);
    cs[n * 65 + q * 4 + 0] = v.x;
    cs[n * 65 + q * 4 + 1] = v.y;
    cs[n * 65 + q * 4 + 2] = v.z;
    cs[n * 65 + q * 4 + 3] = v.w;
  }
  for (int i = tid; i < NGRP; i += 256) gij[i] = g_gij[i];
  if (tid < 64) { csqs[tid] = g_csq[tid]; bsm[tid] = g_bsum[tid]; }
  __syncthreads();
  if (tid < 64) {
    float s = 0.f;
    const float* zr = zs + tid * 68;
    for (int d = 0; d < 64; ++d) s = fmaf(zr[d], zr[d], s);
    zsq[tid] = s;
  }

  const int grow = tid >> 2, qtr = tid & 3;        // X-gen role
  const float* zrow = zs + grow * 68;

  const int wm = w >> 1, wn = w & 1;               // 4m x 2n warp grid
  const int m_base = wm * 16, n_base = wn * 32;
  float acc[4][4] = {};

  // X generator for chunk ch into buffer buf (all regions)
  auto genX = [&](int ch, int buf) {
    __nv_bfloat16* xhd = Xh + buf * 4608 + grow * 72 + qtr * 16;
    __nv_bfloat16* xld = Xl + buf * 4608 + grow * 72 + qtr * 16;
    const int pb = ch * 64 + qtr * 16;
#pragma unroll
    for (int g = 0; g < 2; ++g) {
      const int p = pb + g * 8;
      float v[8];
      float4 u0, u1;
      float scale = 1.f;
      if (p < 64) {                        // z region (chunk 0)
        u0 = *(const float4*)(zrow + p);
        u1 = *(const float4*)(zrow + p + 4);
      } else if (p < 320) {                // feat region (chunks 1..4)
        const float* fp = feat + (size_t)(r0 + grow) * 256 + (p - 64);
        u0 = *(const float4*)fp; u1 = *(const float4*)(fp + 4);
      } else {                             // zz aligned-group region
        uchar2 ij = gij[(p - 320) >> 3];
        scale = zrow[ij.x];
        u0 = *(const float4*)(zrow + ij.y);
        u1 = *(const float4*)(zrow + ij.y + 4);
      }
      v[0] = scale * u0.x; v[1] = scale * u0.y;
      v[2] = scale * u0.z; v[3] = scale * u0.w;
      v[4] = scale * u1.x; v[5] = scale * u1.y;
      v[6] = scale * u1.z; v[7] = scale * u1.w;
      split_store(xhd + g * 8, xld + g * 8, v);
    }
  };

  const uint4* WfH = (const uint4*)g_WfH;
  const uint4* WfL = (const uint4*)g_WfL;
  uint4 wh4[4][2], wl4[4][2];                      // [kh][nb2]
#pragma unroll
  for (int kh = 0; kh < 4; ++kh)
#pragma unroll
    for (int nb2 = 0; nb2 < 2; ++nb2) {
      int idx = ((0 * 4 + kh) * 4 + wn * 2 + nb2) * 32 + lane;
      wh4[kh][nb2] = WfH[idx];
      wl4[kh][nb2] = WfL[idx];
    }

  // prologue: chunks 0 and 1 into bufs 0 and 1
  genX(0, 0);
  genX(1, 1);
  __syncthreads();

  const uint32_t aoff = ((lane & 15) * 72 + (lane >> 4) * 8) * 2;
  const uint32_t XHb = smb + O_XH + m_base * 144 + aoff;
  const uint32_t XLb = smb + O_XL + m_base * 144 + aoff;

  for (int c = 0; c < NCH; ++c) {
    const int cb = c & 3;
    // ---- MMA on buf cb (3-pass split); W from registers ----
    const uint32_t xh0 = XHb + cb * 9216, xl0 = XLb + cb * 9216;
#pragma unroll
    for (int kh = 0; kh < 4; ++kh) {
      const uint32_t kb = kh * 32;
      uint32_t ah[4], al[4];
      ldsm4(ah, xh0 + kb);
      ldsm4(al, xl0 + kb);
#pragma unroll
      for (int nb2 = 0; nb2 < 2; ++nb2) {
        const uint32_t* bh = (const uint32_t*)&wh4[kh][nb2];
        const uint32_t* bl = (const uint32_t*)&wl4[kh][nb2];
#pragma unroll
        for (int ntl = 0; ntl < 2; ++ntl) {
          const int nt = nb2 * 2 + ntl;
          mma16816(acc[nt], ah, bh + ntl * 2);
          mma16816(acc[nt], ah, bl + ntl * 2);
          mma16816(acc[nt], al, bh + ntl * 2);
        }
      }
    }
    // prefetch W for chunk c+1 (regs already consumed above)
    if (c + 1 < NCH) {
#pragma unroll
      for (int kh = 0; kh < 4; ++kh)
#pragma unroll
        for (int nb2 = 0; nb2 < 2; ++nb2) {
          int idx = (((c + 1) * 4 + kh) * 4 + wn * 2 + nb2) * 32 + lane;
          wh4[kh][nb2] = WfH[idx];
          wl4[kh][nb2] = WfL[idx];
        }
    }
    // produce X chunk c+2 into buf (c+2)&3
    if (c + 2 < NCH) genX(c + 2, (c + 2) & 3);
    if (c & 1) __syncthreads();
  }
  __syncthreads();   // ensure all MMA reads done before Sc overlays X

  // ---- epilogue: fp32 z.c, hyperbolic score (Sc overlaps dead X buffer) ----
  const int colA = n_base + tg * 2;
  const int row0 = m_base + gid, row1 = row0 + 8;
  {
    float zcq[2][8];
#pragma unroll
    for (int r = 0; r < 2; ++r)
#pragma unroll
      for (int q = 0; q < 8; ++q) zcq[r][q] = 0.f;
    const float* z0 = zs + row0 * 68;
    const float* z1 = zs + row1 * 68;
    const float* cp[8];
#pragma unroll
    for (int nt = 0; nt < 4; ++nt) {
      cp[nt * 2]     = cs + (colA + nt * 8) * 65;
      cp[nt * 2 + 1] = cs + (colA + nt * 8 + 1) * 65;
    }
    for (int d = 0; d < 64; ++d) {
      float a0 = z0[d], a1 = z1[d];
#pragma unroll
      for (int q = 0; q < 8; ++q) {
        float b = cp[q][d];
        zcq[0][q] = fmaf(a0, b, zcq[0][q]);
        zcq[1][q] = fmaf(a1, b, zcq[1][q]);
      }
    }
#pragma unroll
    for (int nt = 0; nt < 4; ++nt) {
#pragma unroll
      for (int q = 0; q < 4; ++q) {
        const int rh = q >> 1;
        const int row = rh ? row1 : row0;
        const int col = colA + nt * 8 + (q & 1);
        const float gem = acc[nt][q];
        const float zq = zsq[row], cq2 = csqs[col];
        const float zcv = zcq[rh][nt * 2 + (q & 1)];
        float dsq = zq + cq2 - 2.f * zcv;
        float denom = (1.f - zq) * (1.f - cq2) + 1e-3f;
        float arg = fmaxf(1.f + 2.f * dsq / denom, 1.001f);
        float dist = logf(arg + sqrtf((arg + 1.f) * (arg - 1.f)));
        float tau = fmaxf(SQRTK * fmaxf(1.f - zq, 1e-3f) * 0.5f, 0.01f);
        float r2 = fminf(zq, 0.999f);
        float invlam = (1.f - r2 + 1e-3f) * 0.5f;
        Sc[row * 68 + col] =
            -dist / tau + (gem + bsm[col]) * invlam * (1.f / SQRTK);
      }
    }
  }
  __syncthreads();

  // ---- softmax + argmax ----
  const bool has_k = (out_size >= BTOT * 64 + BTOT);
  if (tid < 64) {
    float m = -1e30f; int am = 0;
    const float* sr = Sc + tid * 68;
    for (int n = 0; n < 64; ++n) {
      float v = sr[n];
      if (v > m) { m = v; am = n; }
    }
    float s = 0.f;
    for (int n = 0; n < 64; ++n) s += __expf(sr[n] - m);
    rmx[tid] = m;
    riv[tid] = 1.f / s;
    if (has_k) out[BTOT * 64 + r0 + tid] = (float)am;
  }
  __syncthreads();
  for (int i = tid; i < 1024; i += 256) {           // 64 rows x 16 float4
    int r = i >> 4, q = i & 15;
    float mv = rmx[r], iv = riv[r];
    const float* sr = Sc + r * 68 + q * 4;
    float4 o;
    o.x = __expf(sr[0] - mv) * iv;
    o.y = __expf(sr[1] - mv) * iv;
    o.z = __expf(sr[2] - mv) * iv;
    o.w = __expf(sr[3] - mv) * iv;
    *(float4*)(out + (size_t)(r0 + r) * 64 + q * 4) = o;
  }
}

// ----------------------------------------------------------------------------
extern "C" void kernel_launch(void* const* d_in, const int* in_sizes, int n_in,
                              void* d_out, int out_size) {
  const float* z    = (const float*)d_in[0];
  const float* feat = (const float*)d_in[1];
  const float* qzw  = (const float*)d_in[2];
  const float* qzb  = (const float*)d_in[3];
  const float* qfw  = (const float*)d_in[4];
  const float* qfb  = (const float*)d_in[5];
  const float* qg   = (const float*)d_in[6];
  const float* cq   = (const float*)d_in[7];
  float* out = (float*)d_out;

  prep_fold1<<<dim3(PFULL / 32, NSPL), 256>>>(qzw, qfw, qg, cq);
  prep_sum<<<(PFULL * 64 / 4) / 256, 256>>>();
  prep_fold2<<<dim3(NCH, 4), 256>>>(cq, qzb, qfb);
  cudaFuncSetAttribute(atlas_main, cudaFuncAttributeMaxDynamicSharedMemorySize,
                       SMEMB);
  atlas_main<<<BTOT / 64, 256, SMEMB>>>(z, feat, cq, out, out_size);
}

// round 17
// speedup vs baseline: 1.4080x; 1.0073x over previous
#include <cuda_runtime.h>
#include <cuda_bf16.h>
#include <cstdint>

#define BTOT 16384
#define PFULL 4416          // 64 z + 256 feat + 4096 zz (full)
#define PW2   2624          // 64 z + 256 feat + 2304 zz (8-aligned tri groups)
#define NGRP  288
#define NCH   41            // PW2 / 64
#define NSPL  8
#define SQRTK 11.313708498984761f

__device__ float g_WpartT[NSPL][64 * PFULL];   // [split][n][p]
__device__ float g_Wsum[64 * PFULL];           // [n][p]
// W in mma B-fragment order: [c][kh][nb16][lane] -> uint4 (8 bf16)
__device__ __align__(16) __nv_bfloat16 g_WfH[NCH * 512 * 8];
__device__ __align__(16) __nv_bfloat16 g_WfL[NCH * 512 * 8];
__device__ float g_csq[64];
__device__ float g_bsum[64];
__device__ uchar2 g_gij[NGRP];

// ---- prep stage 1: fold over K (split-k 8), [n][p] coalesced output --------
__global__ void prep_fold1(const float* __restrict__ qzw,
                           const float* __restrict__ qfw,
                           const float* __restrict__ qg,
                           const float* __restrict__ cq) {
  __shared__ float cq_s[64 * 16];
  const int tid = threadIdx.x;
  const int kbase = blockIdx.y * 16;
  for (int i = tid; i < 256; i += 256) {
    int row = i >> 2, q = i & 3;
    *(float4*)(cq_s + row * 16 + q * 4) =
        *(const float4*)(cq + row * 128 + kbase + q * 4);
  }
  __syncthreads();

  const int p  = blockIdx.x * 32 + (tid & 7) * 4;
  const int ng = tid >> 3;            // 32 groups x 2 charts
  const float* src; int stride, off;
  if (p < 64)       { src = qzw; stride = 64;   off = p; }
  else if (p < 320) { src = qfw; stride = 256;  off = p - 64; }
  else              { src = qg;  stride = 4096; off = p - 320; }
  src += (size_t)kbase * stride;

  float acc[2][4] = {};
  for (int k0 = 0; k0 < 16; k0 += 8) {
    float4 wv[8];
#pragma unroll
    for (int kk = 0; kk < 8; ++kk)
      wv[kk] = *(const float4*)(src + (size_t)(k0 + kk) * stride + off);
#pragma unroll
    for (int kk = 0; kk < 8; ++kk) {
#pragma unroll
      for (int j = 0; j < 2; ++j) {
        float cv = cq_s[(ng * 2 + j) * 16 + k0 + kk];
        acc[j][0] = fmaf(cv, wv[kk].x, acc[j][0]);
        acc[j][1] = fmaf(cv, wv[kk].y, acc[j][1]);
        acc[j][2] = fmaf(cv, wv[kk].z, acc[j][2]);
        acc[j][3] = fmaf(cv, wv[kk].w, acc[j][3]);
      }
    }
  }
  float* dst = g_WpartT[blockIdx.y];
#pragma unroll
  for (int j = 0; j < 2; ++j)
    *(float4*)(dst + (size_t)(ng * 2 + j) * PFULL + p) = *(float4*)acc[j];
}

// ---- prep stage 1b: sum the 8 split partials (fully coalesced) -------------
__global__ void prep_sum() {
  size_t idx = (size_t)blockIdx.x * 256 + threadIdx.x;   // float4 index
  float4 s = make_float4(0.f, 0.f, 0.f, 0.f);
#pragma unroll
  for (int sp = 0; sp < NSPL; ++sp) {
    float4 u = ((const float4*)g_WpartT[sp])[idx];
    s.x += u.x; s.y += u.y; s.z += u.z; s.w += u.w;
  }
  ((float4*)g_Wsum)[idx] = s;
}

// ---- prep stage 2: tri-fold, hi/lo split, FRAGMENT layout (+small) ---------
__global__ void prep_fold2(const float* __restrict__ cq,
                           const float* __restrict__ qzb,
                           const float* __restrict__ qfb) {
  const int tid = threadIdx.x;
  const int pl = blockIdx.x * 64 + (tid & 15) * 4;   // quad of p
  const int n  = blockIdx.y * 16 + (tid >> 4);
  const float* wn = g_Wsum + (size_t)n * PFULL;

  float w4[4];
  if (pl < 320) {
    float4 u = *(const float4*)(wn + pl);
    w4[0] = u.x; w4[1] = u.y; w4[2] = u.z; w4[3] = u.w;
  } else {
    int t = pl - 320;
    int g = t >> 3;
    int i = 0, cum = 0;
    for (int ii = 0; ii < 64; ++ii) {
      int cnt = 8 - (ii >> 3);
      if (g < cum + cnt) { i = ii; break; }
      cum += cnt;
    }
    int b = (i >> 3) + (g - cum);
    int j0 = b * 8 + (t & 7);
    if (blockIdx.y == 0 && (tid >> 4) == 0 && (t & 7) == 0)
      g_gij[g] = make_uchar2((unsigned char)i, (unsigned char)(b * 8));
    float4 u = *(const float4*)(wn + 320 + i * 64 + j0);
    float tmp[4] = {u.x, u.y, u.z, u.w};
#pragma unroll
    for (int q = 0; q < 4; ++q) {
      int jq = j0 + q;
      if (jq > i)       w4[q] = tmp[q] + wn[320 + jq * 64 + i];
      else if (jq == i) w4[q] = tmp[q];
      else              w4[q] = 0.f;
    }
  }
#pragma unroll
  for (int q = 0; q < 4; ++q) {
    int plq = pl + q;
    int c = plq >> 6, kc = plq & 63, kh = kc >> 4, kr = kc & 15;
    int tg = (kr >> 1) & 3, hik = (kr >> 3) & 1, pair = kr & 1;
    __nv_bfloat16 h = __float2bfloat16(w4[q]);
    __nv_bfloat16 l = __float2bfloat16(w4[q] - __bfloat162float(h));
    size_t eidx = ((size_t)((c * 4 + kh) * 4 + (n >> 4)) * 256) +
                  ((n & 7) * 4 + tg) * 8 + ((n >> 3) & 1) * 4 + hik * 2 + pair;
    g_WfH[eidx] = h;
    g_WfL[eidx] = l;
  }

  // merged prep_small
  if (blockIdx.x == 0 && blockIdx.y == 0) {
    const int nn = tid >> 2, q = tid & 3;
    const float* r = cq + nn * 128;
    float cs = 0.f, bs = 0.f;
    for (int d = q * 16; d < q * 16 + 16; ++d) cs = fmaf(r[d], r[d], cs);
    for (int k = q * 32; k < q * 32 + 32; ++k)
      bs = fmaf(r[k], qzb[k] + qfb[k], bs);
    cs += __shfl_xor_sync(0xffffffffu, cs, 1);
    cs += __shfl_xor_sync(0xffffffffu, cs, 2);
    bs += __shfl_xor_sync(0xffffffffu, bs, 1);
    bs += __shfl_xor_sync(0xffffffffu, bs, 2);
    if (q == 0) { g_csq[nn] = cs; g_bsum[nn] = bs; }
  }
}

// --------------------------- main kernel (R15-proven, 77.7us) ---------------
// 64 rows/CTA, grid 256, 2 CTAs/SM; (4m,2n) warps; W reg-resident;
// 2-buffer X, one barrier per chunk.
#define O_ZS   0             // float [64][68] = 17408
#define O_CS   17408         // float [64][65] = 16640
#define O_GIJ  34048         // uchar2[288] = 576
#define O_ZSQ  34624
#define O_CSQ  34880
#define O_BSM  35136
#define O_RMX  35392
#define O_RIV  35648
#define O_XH   35904         // bf16 [2][64][72] = 18432  (Sc overlaps here)
#define O_XL   54336         // bf16 [2][64][72] = 18432
#define SMEMB  72768

__device__ __forceinline__ void mma16816(float* c, const uint32_t* a,
                                         const uint32_t* b) {
  asm volatile(
      "mma.sync.aligned.m16n8k16.row.col.f32.bf16.bf16.f32 "
      "{%0,%1,%2,%3},{%4,%5,%6,%7},{%8,%9},{%0,%1,%2,%3};"
      : "+f"(c[0]), "+f"(c[1]), "+f"(c[2]), "+f"(c[3])
      : "r"(a[0]), "r"(a[1]), "r"(a[2]), "r"(a[3]), "r"(b[0]), "r"(b[1]));
}

__device__ __forceinline__ void ldsm4(uint32_t* r, uint32_t saddr) {
  asm volatile(
      "ldmatrix.sync.aligned.m8n8.x4.shared.b16 {%0,%1,%2,%3},[%4];"
      : "=r"(r[0]), "=r"(r[1]), "=r"(r[2]), "=r"(r[3]) : "r"(saddr));
}

__device__ __forceinline__ void split_store(__nv_bfloat16* xh, __nv_bfloat16* xl,
                                            const float* v) {
  uint32_t ph[4], plo[4];
#pragma unroll
  for (int j = 0; j < 4; ++j) {
    __nv_bfloat162 h2 = __float22bfloat162_rn(make_float2(v[2 * j], v[2 * j + 1]));
    ph[j] = *(uint32_t*)&h2;
    __nv_bfloat162 l2 = __float22bfloat162_rn(
        make_float2(v[2 * j] - __low2float(h2), v[2 * j + 1] - __high2float(h2)));
    plo[j] = *(uint32_t*)&l2;
  }
  *(uint4*)xh = *(uint4*)ph;
  *(uint4*)xl = *(uint4*)plo;
}

__global__ void __launch_bounds__(256, 2)
atlas_main(const float* __restrict__ z, const float* __restrict__ feat,
           const float* __restrict__ cq, float* __restrict__ out,
           int out_size) {
  extern __shared__ char sm[];
  float* zs = (float*)(sm + O_ZS);                 // stride 68
  float* cs = (float*)(sm + O_CS);                 // stride 65
  uchar2* gij = (uchar2*)(sm + O_GIJ);
  float* zsq  = (float*)(sm + O_ZSQ);
  float* csqs = (float*)(sm + O_CSQ);
  float* bsm  = (float*)(sm + O_BSM);
  float* rmx  = (float*)(sm + O_RMX);
  float* riv  = (float*)(sm + O_RIV);
  float* Sc   = (float*)(sm + O_XH);               // overlap, used post-MMA
  __nv_bfloat16* Xh = (__nv_bfloat16*)(sm + O_XH); // per-buf 4608 elem
  __nv_bfloat16* Xl = (__nv_bfloat16*)(sm + O_XL);

  const int tid = threadIdx.x, lane = tid & 31, w = tid >> 5;
  const int gid = lane >> 2, tg = lane & 3;
  const int r0 = blockIdx.x * 64;
  const uint32_t smb = (uint32_t)__cvta_generic_to_shared(sm);

  for (int i = tid; i < 1024; i += 256) {          // 64 rows x 16 float4
    int row = i >> 4, q = i & 15;
    *(float4*)(zs + row * 68 + q * 4) =
        ((const float4*)(z + (size_t)(r0 + row) * 64))[q];
  }
  for (int i = tid; i < 1024; i += 256) {          // centers 64x64
    int n = i >> 4, q = i & 15;
    float4 v = *(const float4*)(cq + n * 128 + q * 4);
    cs[n * 65 + q * 4 + 0] = v.x;
    cs[n * 65 + q * 4 + 1] = v.y;
    cs[n * 65 + q * 4 + 2] = v.z;
    cs[n * 65 + q * 4 + 3] = v.w;
  }
  for (int i = tid; i < NGRP; i += 256) gij[i] = g_gij[i];
  if (tid < 64) { csqs[tid] = g_csq[tid]; bsm[tid] = g_bsum[tid]; }
  __syncthreads();
  if (tid < 64) {
    float s = 0.f;
    const float* zr = zs + tid * 68;
    for (int d = 0; d < 64; ++d) s = fmaf(zr[d], zr[d], s);
    zsq[tid] = s;
  }

  const int grow = tid >> 2, qtr = tid & 3;        // X-gen role
  const float* zrow = zs + grow * 68;

  const int wm = w >> 1, wn = w & 1;               // 4m x 2n warp grid
  const int m_base = wm * 16, n_base = wn * 32;
  float acc[4][4] = {};

  const uint4* WfH = (const uint4*)g_WfH;
  const uint4* WfL = (const uint4*)g_WfL;
  uint4 wh4[4][2], wl4[4][2];                      // [kh][nb2]
  // preload W fragments for chunk 0
#pragma unroll
  for (int kh = 0; kh < 4; ++kh)
#pragma unroll
    for (int nb2 = 0; nb2 < 2; ++nb2) {
      int idx = ((0 * 4 + kh) * 4 + wn * 2 + nb2) * 32 + lane;
      wh4[kh][nb2] = WfH[idx];
      wl4[kh][nb2] = WfL[idx];
    }

  // prologue: chunk 0 (pure z region) X into buf 0
  {
#pragma unroll
    for (int g = 0; g < 2; ++g) {
      int pb = qtr * 16 + g * 8;
      float v[8];
      float4 u0 = *(const float4*)(zrow + pb);
      float4 u1 = *(const float4*)(zrow + pb + 4);
      v[0] = u0.x; v[1] = u0.y; v[2] = u0.z; v[3] = u0.w;
      v[4] = u1.x; v[5] = u1.y; v[6] = u1.z; v[7] = u1.w;
      split_store(Xh + grow * 72 + pb, Xl + grow * 72 + pb, v);
    }
  }
  __syncthreads();

  const uint32_t aoff = ((lane & 15) * 72 + (lane >> 4) * 8) * 2;
  const uint32_t XHb = smb + O_XH + m_base * 144 + aoff;
  const uint32_t XLb = smb + O_XL + m_base * 144 + aoff;

  for (int c = 0; c < NCH; ++c) {
    const int cb = c & 1, nb = cb ^ 1, cc = c + 1;
    // ---- MMA on buf cb (3-pass split); W from registers ----
    const uint32_t xh0 = XHb + cb * 9216, xl0 = XLb + cb * 9216;
#pragma unroll
    for (int kh = 0; kh < 4; ++kh) {
      const uint32_t kb = kh * 32;
      uint32_t ah[4], al[4];
      ldsm4(ah, xh0 + kb);
      ldsm4(al, xl0 + kb);
#pragma unroll
      for (int nb2 = 0; nb2 < 2; ++nb2) {
        const uint32_t* bh = (const uint32_t*)&wh4[kh][nb2];
        const uint32_t* bl = (const uint32_t*)&wl4[kh][nb2];
#pragma unroll
        for (int ntl = 0; ntl < 2; ++ntl) {
          const int nt = nb2 * 2 + ntl;
          mma16816(acc[nt], ah, bh + ntl * 2);
          mma16816(acc[nt], ah, bl + ntl * 2);
          mma16816(acc[nt], al, bh + ntl * 2);
        }
      }
    }
    if (cc < NCH) {
      // overwrite W regs with next chunk (MMA above already consumed them)
#pragma unroll
      for (int kh = 0; kh < 4; ++kh)
#pragma unroll
        for (int nb2 = 0; nb2 < 2; ++nb2) {
          int idx = ((cc * 4 + kh) * 4 + wn * 2 + nb2) * 32 + lane;
          wh4[kh][nb2] = WfH[idx];
          wl4[kh][nb2] = WfL[idx];
        }
      // produce X chunk cc into buf nb
      __nv_bfloat16* xhd = Xh + nb * 4608 + grow * 72 + qtr * 16;
      __nv_bfloat16* xld = Xl + nb * 4608 + grow * 72 + qtr * 16;
      const int pb = cc * 64 + qtr * 16;
#pragma unroll
      for (int g = 0; g < 2; ++g) {
        const int p = pb + g * 8;
        float v[8];
        float4 u0, u1;
        float scale = 1.f;
        if (p < 320) {                     // feat region (chunks 1..4)
          const float* fp = feat + (size_t)(r0 + grow) * 256 + (p - 64);
          u0 = *(const float4*)fp; u1 = *(const float4*)(fp + 4);
        } else {                           // zz aligned-group region
          uchar2 ij = gij[(p - 320) >> 3];
          scale = zrow[ij.x];
          u0 = *(const float4*)(zrow + ij.y);
          u1 = *(const float4*)(zrow + ij.y + 4);
        }
        v[0] = scale * u0.x; v[1] = scale * u0.y;
        v[2] = scale * u0.z; v[3] = scale * u0.w;
        v[4] = scale * u1.x; v[5] = scale * u1.y;
        v[6] = scale * u1.z; v[7] = scale * u1.w;
        split_store(xhd + g * 8, xld + g * 8, v);
      }
    }
    __syncthreads();
  }

  // ---- epilogue: fp32 z.c, hyperbolic score (Sc overlaps dead X buffer) ----
  const int colA = n_base + tg * 2;
  const int row0 = m_base + gid, row1 = row0 + 8;
  {
    float zcq[2][8];
#pragma unroll
    for (int r = 0; r < 2; ++r)
#pragma unroll
      for (int q = 0; q < 8; ++q) zcq[r][q] = 0.f;
    const float* z0 = zs + row0 * 68;
    const float* z1 = zs + row1 * 68;
    const float* cp[8];
#pragma unroll
    for (int nt = 0; nt < 4; ++nt) {
      cp[nt * 2]     = cs + (colA + nt * 8) * 65;
      cp[nt * 2 + 1] = cs + (colA + nt * 8 + 1) * 65;
    }
    for (int d = 0; d < 64; ++d) {
      float a0 = z0[d], a1 = z1[d];
#pragma unroll
      for (int q = 0; q < 8; ++q) {
        float b = cp[q][d];
        zcq[0][q] = fmaf(a0, b, zcq[0][q]);
        zcq[1][q] = fmaf(a1, b, zcq[1][q]);
      }
    }
#pragma unroll
    for (int nt = 0; nt < 4; ++nt) {
#pragma unroll
      for (int q = 0; q < 4; ++q) {
        const int rh = q >> 1;
        const int row = rh ? row1 : row0;
        const int col = colA + nt * 8 + (q & 1);
        const float gem = acc[nt][q];
        const float zq = zsq[row], cq2 = csqs[col];
        const float zcv = zcq[rh][nt * 2 + (q & 1)];
        float dsq = zq + cq2 - 2.f * zcv;
        float denom = (1.f - zq) * (1.f - cq2) + 1e-3f;
        float arg = fmaxf(1.f + 2.f * dsq / denom, 1.001f);
        float dist = logf(arg + sqrtf((arg + 1.f) * (arg - 1.f)));
        float tau = fmaxf(SQRTK * fmaxf(1.f - zq, 1e-3f) * 0.5f, 0.01f);
        float r2 = fminf(zq, 0.999f);
        float invlam = (1.f - r2 + 1e-3f) * 0.5f;
        Sc[row * 68 + col] =
            -dist / tau + (gem + bsm[col]) * invlam * (1.f / SQRTK);
      }
    }
  }
  __syncthreads();

  // ---- softmax + argmax ----
  const bool has_k = (out_size >= BTOT * 64 + BTOT);
  if (tid < 64) {
    float m = -1e30f; int am = 0;
    const float* sr = Sc + tid * 68;
    for (int n = 0; n < 64; ++n) {
      float v = sr[n];
      if (v > m) { m = v; am = n; }
    }
    float s = 0.f;
    for (int n = 0; n < 64; ++n) s += __expf(sr[n] - m);
    rmx[tid] = m;
    riv[tid] = 1.f / s;
    if (has_k) out[BTOT * 64 + r0 + tid] = (float)am;
  }
  __syncthreads();
  for (int i = tid; i < 1024; i += 256) {           // 64 rows x 16 float4
    int r = i >> 4, q = i & 15;
    float mv = rmx[r], iv = riv[r];
    const float* sr = Sc + r * 68 + q * 4;
    float4 o;
    o.x = __expf(sr[0] - mv) * iv;
    o.y = __expf(sr[1] - mv) * iv;
    o.z = __expf(sr[2] - mv) * iv;
    o.w = __expf(sr[3] - mv) * iv;
    *(float4*)(out + (size_t)(r0 + r) * 64 + q * 4) = o;
  }
}

// ----------------------------------------------------------------------------
extern "C" void kernel_launch(void* const* d_in, const int* in_sizes, int n_in,
                              void* d_out, int out_size) {
  const float* z    = (const float*)d_in[0];
  const float* feat = (const float*)d_in[1];
  const float* qzw  = (const float*)d_in[2];
  const float* qzb  = (const float*)d_in[3];
  const float* qfw  = (const float*)d_in[4];
  const float* qfb  = (const float*)d_in[5];
  const float* qg   = (const float*)d_in[6];
  const float* cq   = (const float*)d_in[7];
  float* out = (float*)d_out;

  prep_fold1<<<dim3(PFULL / 32, NSPL), 256>>>(qzw, qfw, qg, cq);
  prep_sum<<<(PFULL * 64 / 4) / 256, 256>>>();
  prep_fold2<<<dim3(NCH, 4), 256>>>(cq, qzb, qfb);
  cudaFuncSetAttribute(atlas_main, cudaFuncAttributeMaxDynamicSharedMemorySize,
                       SMEMB);
  atlas_main<<<BTOT / 64, 256, SMEMB>>>(z, feat, cq, out, out_size);
}